// round 10
// baseline (speedup 1.0000x reference)
#include <cuda_runtime.h>
#include <cuda_fp16.h>
#include <cstdint>

// N=50000, E=1600000, F=128, H=128, C=64
#define NMAX 50000
#define EMAX 1600000
#define SCAN_B 1024

// Scratch (no dynamic allocation allowed)
__device__ __align__(16) float  g_dinv[NMAX];
__device__ __align__(16) int    g_count[NMAX];
__device__ __align__(16) int    g_rowstart[NMAX + 1];
__device__ __align__(16) int    g_rank[EMAX];
__device__ __align__(16) int    g_blocksum[(NMAX + SCAN_B - 1) / SCAN_B + 1];
__device__ __align__(16) int    g_srcs[EMAX];
__device__ __align__(16) __half g_msg [(size_t)NMAX * 128];  // msg1 = x@W1 (unscaled)
__device__ __align__(16) __half g_h1h [(size_t)NMAX * 128];  // h1 post-relu (fp16)
__device__ __align__(16) __half g_msg2[(size_t)NMAX * 64];   // msg2 = (h1@W2)*dinv

// ---------------- CSR build ----------------

__global__ void k_zero_int(int* p, int n) {
    int i = blockIdx.x * blockDim.x + threadIdx.x;
    if (i < n) p[i] = 0;
}

__global__ void k_hist(const int* __restrict__ dst, int* __restrict__ count,
                       int* __restrict__ rank, int E, int n) {
    int e = blockIdx.x * blockDim.x + threadIdx.x;
    if (e < E) {
        int d = dst[e];
        int r = 0;
        if ((unsigned)d < (unsigned)n) r = atomicAdd(&count[d], 1);
        rank[e] = r;
    }
}

__global__ void k_scan1(const int* __restrict__ count, int* __restrict__ rowstart,
                        int* __restrict__ blocksum, int n) {
    __shared__ int buf[SCAN_B];
    int i = blockIdx.x * SCAN_B + threadIdx.x;
    int v = (i < n) ? count[i] : 0;
    buf[threadIdx.x] = v;
    __syncthreads();
#pragma unroll
    for (int off = 1; off < SCAN_B; off <<= 1) {
        int t = 0;
        if ((int)threadIdx.x >= off) t = buf[threadIdx.x - off];
        __syncthreads();
        if ((int)threadIdx.x >= off) buf[threadIdx.x] += t;
        __syncthreads();
    }
    if (i < n) rowstart[i] = buf[threadIdx.x] - v;
    if (threadIdx.x == SCAN_B - 1) blocksum[blockIdx.x] = buf[SCAN_B - 1];
}

// scan3 with fused blocksum prefix (warp 0 re-derives the 49-entry exclusive scan)
__global__ void k_scan3(const int* __restrict__ count, int* __restrict__ rowstart,
                        const int* __restrict__ blocksum, float* __restrict__ dinv,
                        int n, int E, int nb) {
    __shared__ int pref[64];
    if (threadIdx.x < 32) {
        int lane = threadIdx.x;
        int carry = 0;
        for (int base = 0; base < nb; base += 32) {
            int i = base + lane;
            int v = (i < nb) ? blocksum[i] : 0;
            int x = v;
#pragma unroll
            for (int off = 1; off < 32; off <<= 1) {
                int t = __shfl_up_sync(0xffffffffu, x, off);
                if (lane >= off) x += t;
            }
            if (i < nb) pref[i] = carry + x - v;   // exclusive
            carry += __shfl_sync(0xffffffffu, x, 31);
        }
    }
    __syncthreads();
    int i = blockIdx.x * blockDim.x + threadIdx.x;
    if (i < n) {
        rowstart[i] += pref[i / SCAN_B];
        dinv[i] = rsqrtf((float)count[i] + 1.0f);
    }
    if (i == 0) rowstart[n] = E;
}

__global__ void k_fill(const int* __restrict__ src, const int* __restrict__ dst,
                       const int* __restrict__ rowstart, const int* __restrict__ rank,
                       int* __restrict__ srcs, int E, int n) {
    int e = blockIdx.x * blockDim.x + threadIdx.x;
    if (e < E) {
        int d = dst[e];
        int s = src[e];
        if ((unsigned)d < (unsigned)n && (unsigned)s < (unsigned)n)
            srcs[rowstart[d] + rank[e]] = s;
    }
}

// ---------------- tf32 tensor-core GEMMs ----------------

__device__ __forceinline__ uint32_t f2tf32(float f) {
    uint32_t u;
    asm("cvt.rna.tf32.f32 %0, %1;" : "=r"(u) : "f"(f));
    return u;
}

// fp32 input, OUTC=128, no dinv scaling (msg1 = x@W1)
__global__ void k_gemm1_tc(const float* __restrict__ X, const float* __restrict__ W,
                           __half* __restrict__ out, int N) {
    constexpr int OUTC = 128, BM = 128, BK = 32;
    constexpr int AP = 36, WP = OUTC + 4;
    constexpr int WARP_N = OUTC / 2, NNT = WARP_N / 8;
    __shared__ float As[BM * AP];
    __shared__ float Ws[BK * WP];

    const int tid  = threadIdx.x;
    const int warp = tid >> 5, lane = tid & 31;
    const int wm = warp >> 1, wn = warp & 1;
    const int g = lane >> 2, tig = lane & 3;
    const int rowBase = blockIdx.x * BM;

    float acc[2][NNT][4];
#pragma unroll
    for (int mt = 0; mt < 2; mt++)
#pragma unroll
        for (int nt = 0; nt < NNT; nt++)
#pragma unroll
            for (int c = 0; c < 4; c++) acc[mt][nt][c] = 0.f;

    for (int k0 = 0; k0 < 128; k0 += BK) {
#pragma unroll
        for (int j = 0; j < 4; j++) {
            int i4  = tid + j * 256;
            int row = i4 >> 3;
            int col = (i4 & 7) * 4;
            float4 v = make_float4(0.f, 0.f, 0.f, 0.f);
            if (rowBase + row < N)
                v = *((const float4*)(X + (size_t)(rowBase + row) * 128 + k0 + col));
            float* p = &As[row * AP + col];
            p[0] = __uint_as_float(f2tf32(v.x));
            p[1] = __uint_as_float(f2tf32(v.y));
            p[2] = __uint_as_float(f2tf32(v.z));
            p[3] = __uint_as_float(f2tf32(v.w));
        }
#pragma unroll
        for (int j = 0; j < 4; j++) {
            int i4  = tid + j * 256;
            int row = i4 >> 5;
            int col = (i4 & 31) * 4;
            float4 v = *((const float4*)(W + (size_t)(k0 + row) * OUTC + col));
            float* p = &Ws[row * WP + col];
            p[0] = __uint_as_float(f2tf32(v.x));
            p[1] = __uint_as_float(f2tf32(v.y));
            p[2] = __uint_as_float(f2tf32(v.z));
            p[3] = __uint_as_float(f2tf32(v.w));
        }
        __syncthreads();

#pragma unroll
        for (int kk = 0; kk < BK / 8; kk++) {
            int k = kk * 8;
            uint32_t a[2][4];
#pragma unroll
            for (int mt = 0; mt < 2; mt++) {
                int ar = wm * 32 + mt * 16;
                a[mt][0] = __float_as_uint(As[(ar + g)     * AP + k + tig]);
                a[mt][1] = __float_as_uint(As[(ar + g + 8) * AP + k + tig]);
                a[mt][2] = __float_as_uint(As[(ar + g)     * AP + k + tig + 4]);
                a[mt][3] = __float_as_uint(As[(ar + g + 8) * AP + k + tig + 4]);
            }
#pragma unroll
            for (int nt = 0; nt < NNT; nt++) {
                int nc = wn * WARP_N + nt * 8;
                uint32_t b0 = __float_as_uint(Ws[(k + tig)     * WP + nc + g]);
                uint32_t b1 = __float_as_uint(Ws[(k + tig + 4) * WP + nc + g]);
#pragma unroll
                for (int mt = 0; mt < 2; mt++) {
                    asm volatile(
                        "mma.sync.aligned.m16n8k8.row.col.f32.tf32.tf32.f32 "
                        "{%0,%1,%2,%3}, {%4,%5,%6,%7}, {%8,%9}, {%0,%1,%2,%3};"
                        : "+f"(acc[mt][nt][0]), "+f"(acc[mt][nt][1]),
                          "+f"(acc[mt][nt][2]), "+f"(acc[mt][nt][3])
                        : "r"(a[mt][0]), "r"(a[mt][1]), "r"(a[mt][2]), "r"(a[mt][3]),
                          "r"(b0), "r"(b1));
                }
            }
        }
        __syncthreads();
    }

#pragma unroll
    for (int mt = 0; mt < 2; mt++) {
        int r0 = rowBase + wm * 32 + mt * 16 + g;
        int r1 = r0 + 8;
#pragma unroll
        for (int nt = 0; nt < NNT; nt++) {
            int col = wn * WARP_N + nt * 8 + tig * 2;
            if (r0 < N)
                *((__half2*)(out + (size_t)r0 * OUTC + col)) =
                    __floats2half2_rn(acc[mt][nt][0], acc[mt][nt][1]);
            if (r1 < N)
                *((__half2*)(out + (size_t)r1 * OUTC + col)) =
                    __floats2half2_rn(acc[mt][nt][2], acc[mt][nt][3]);
        }
    }
}

// fp16 input, OUTC=64, dinv scaling (msg2 = (h1@W2)*dinv). Operates on a row chunk.
__global__ void k_gemm2_tc(const __half* __restrict__ Xh, const float* __restrict__ W,
                           const float* __restrict__ dinv, __half* __restrict__ out,
                           int Nrows) {
    constexpr int OUTC = 64, BM = 128, BK = 32;
    constexpr int AP = 36, WP = OUTC + 4;
    constexpr int WARP_N = OUTC / 2, NNT = WARP_N / 8;   // 32, 4
    __shared__ float As[BM * AP];
    __shared__ float Ws[BK * WP];

    const int tid  = threadIdx.x;
    const int warp = tid >> 5, lane = tid & 31;
    const int wm = warp >> 1, wn = warp & 1;
    const int g = lane >> 2, tig = lane & 3;
    const int rowBase = blockIdx.x * BM;

    float acc[2][NNT][4];
#pragma unroll
    for (int mt = 0; mt < 2; mt++)
#pragma unroll
        for (int nt = 0; nt < NNT; nt++)
#pragma unroll
            for (int c = 0; c < 4; c++) acc[mt][nt][c] = 0.f;

    for (int k0 = 0; k0 < 128; k0 += BK) {
        // A tile from fp16: 128 rows x 32 halves; uint4 = 8 halves; 512 uint4, 2/thread
#pragma unroll
        for (int j = 0; j < 2; j++) {
            int i4  = tid + j * 256;           // 0..511
            int row = i4 >> 2;
            int c8  = (i4 & 3) * 8;
            uint4 u = make_uint4(0, 0, 0, 0);
            if (rowBase + row < Nrows)
                u = *((const uint4*)(Xh + (size_t)(rowBase + row) * 128 + k0 + c8));
            const __half2* h2 = (const __half2*)&u;
            float* p = &As[row * AP + c8];
#pragma unroll
            for (int q = 0; q < 4; q++) {
                float2 f = __half22float2(h2[q]);
                p[q * 2 + 0] = __uint_as_float(f2tf32(f.x));
                p[q * 2 + 1] = __uint_as_float(f2tf32(f.y));
            }
        }
        // W tile: 32 rows x 64 floats = 512 float4, 2/thread
#pragma unroll
        for (int j = 0; j < 2; j++) {
            int i4  = tid + j * 256;
            int row = i4 >> 4;
            int col = (i4 & 15) * 4;
            float4 v = *((const float4*)(W + (size_t)(k0 + row) * OUTC + col));
            float* p = &Ws[row * WP + col];
            p[0] = __uint_as_float(f2tf32(v.x));
            p[1] = __uint_as_float(f2tf32(v.y));
            p[2] = __uint_as_float(f2tf32(v.z));
            p[3] = __uint_as_float(f2tf32(v.w));
        }
        __syncthreads();

#pragma unroll
        for (int kk = 0; kk < BK / 8; kk++) {
            int k = kk * 8;
            uint32_t a[2][4];
#pragma unroll
            for (int mt = 0; mt < 2; mt++) {
                int ar = wm * 32 + mt * 16;
                a[mt][0] = __float_as_uint(As[(ar + g)     * AP + k + tig]);
                a[mt][1] = __float_as_uint(As[(ar + g + 8) * AP + k + tig]);
                a[mt][2] = __float_as_uint(As[(ar + g)     * AP + k + tig + 4]);
                a[mt][3] = __float_as_uint(As[(ar + g + 8) * AP + k + tig + 4]);
            }
#pragma unroll
            for (int nt = 0; nt < NNT; nt++) {
                int nc = wn * WARP_N + nt * 8;
                uint32_t b0 = __float_as_uint(Ws[(k + tig)     * WP + nc + g]);
                uint32_t b1 = __float_as_uint(Ws[(k + tig + 4) * WP + nc + g]);
#pragma unroll
                for (int mt = 0; mt < 2; mt++) {
                    asm volatile(
                        "mma.sync.aligned.m16n8k8.row.col.f32.tf32.tf32.f32 "
                        "{%0,%1,%2,%3}, {%4,%5,%6,%7}, {%8,%9}, {%0,%1,%2,%3};"
                        : "+f"(acc[mt][nt][0]), "+f"(acc[mt][nt][1]),
                          "+f"(acc[mt][nt][2]), "+f"(acc[mt][nt][3])
                        : "r"(a[mt][0]), "r"(a[mt][1]), "r"(a[mt][2]), "r"(a[mt][3]),
                          "r"(b0), "r"(b1));
                }
            }
        }
        __syncthreads();
    }

#pragma unroll
    for (int mt = 0; mt < 2; mt++) {
        int r0 = rowBase + wm * 32 + mt * 16 + g;
        int r1 = r0 + 8;
        float dv0 = (r0 < Nrows) ? dinv[r0] : 0.f;
        float dv1 = (r1 < Nrows) ? dinv[r1] : 0.f;
#pragma unroll
        for (int nt = 0; nt < NNT; nt++) {
            int col = wn * WARP_N + nt * 8 + tig * 2;
            if (r0 < Nrows)
                *((__half2*)(out + (size_t)r0 * OUTC + col)) =
                    __floats2half2_rn(acc[mt][nt][0] * dv0, acc[mt][nt][1] * dv0);
            if (r1 < Nrows)
                *((__half2*)(out + (size_t)r1 * OUTC + col)) =
                    __floats2half2_rn(acc[mt][nt][2] * dv1, acc[mt][nt][3] * dv1);
        }
    }
}

// ---------------- gathers ----------------
// Layer 1 (chunked): h1h = half(relu((Σ dinv[s]·msg[s] + dinv[n]·msg[n])·dinv[n] + b1))

__global__ void k_gather128h(const __half* __restrict__ g, const int* __restrict__ rowstart,
                             const int* __restrict__ srcs, const float* __restrict__ dinv,
                             const float* __restrict__ bias, __half* __restrict__ out,
                             int base, int cnt) {
    int idx0 = (blockIdx.x * blockDim.x + threadIdx.x) >> 5;
    int lane = threadIdx.x & 31;
    if (idx0 >= cnt) return;
    int node = base + idx0;
    int e0 = rowstart[node], e1 = rowstart[node + 1];
    float dvn = dinv[node];

    float acc0, acc1, acc2, acc3;
    {
        uint2 u = *((const uint2*)(g + (size_t)node * 128 + lane * 4));
        float2 a = __half22float2(*(const __half2*)&u.x);
        float2 b = __half22float2(*(const __half2*)&u.y);
        acc0 = dvn * a.x; acc1 = dvn * a.y; acc2 = dvn * b.x; acc3 = dvn * b.y;
    }
    int e = e0;
    while (e1 - e >= 32) {
        int idx = srcs[e + lane];
        float dvl = dinv[idx];
#pragma unroll
        for (int k = 0; k < 32; k++) {
            int s    = __shfl_sync(0xffffffffu, idx, k);
            float ds = __shfl_sync(0xffffffffu, dvl, k);
            uint2 u = *((const uint2*)(g + (size_t)s * 128 + lane * 4));
            float2 a = __half22float2(*(const __half2*)&u.x);
            float2 b = __half22float2(*(const __half2*)&u.y);
            acc0 += ds * a.x; acc1 += ds * a.y; acc2 += ds * b.x; acc3 += ds * b.y;
        }
        e += 32;
    }
    if (e < e1) {
        int m = e1 - e;
        int idx = (lane < m) ? srcs[e + lane] : 0;
        float dvl = (lane < m) ? dinv[idx] : 0.f;
#pragma unroll 8
        for (int k = 0; k < m; k++) {
            int s    = __shfl_sync(0xffffffffu, idx, k);
            float ds = __shfl_sync(0xffffffffu, dvl, k);
            uint2 u = *((const uint2*)(g + (size_t)s * 128 + lane * 4));
            float2 a = __half22float2(*(const __half2*)&u.x);
            float2 b = __half22float2(*(const __half2*)&u.y);
            acc0 += ds * a.x; acc1 += ds * a.y; acc2 += ds * b.x; acc3 += ds * b.y;
        }
    }
    float4 bv = ((const float4*)bias)[lane];
    __half2 h01 = __floats2half2_rn(fmaxf(acc0 * dvn + bv.x, 0.f),
                                    fmaxf(acc1 * dvn + bv.y, 0.f));
    __half2 h23 = __floats2half2_rn(fmaxf(acc2 * dvn + bv.z, 0.f),
                                    fmaxf(acc3 * dvn + bv.w, 0.f));
    uint2 st;
    st.x = *(const uint32_t*)&h01;
    st.y = *(const uint32_t*)&h23;
    *((uint2*)(out + (size_t)node * 128 + lane * 4)) = st;
}

// Layer 2: out = (Σ msg2[s] + msg2[n])·dinv[n] + b2   (msg2 already dinv-scaled)
__global__ void k_gather64h(const __half* __restrict__ g, const int* __restrict__ rowstart,
                            const int* __restrict__ srcs, const float* __restrict__ dinv,
                            const float* __restrict__ bias, float* __restrict__ out, int n) {
    int node = (blockIdx.x * blockDim.x + threadIdx.x) >> 5;
    int lane = threadIdx.x & 31;
    if (node >= n) return;
    int e0 = rowstart[node], e1 = rowstart[node + 1];

    float2 acc = __half22float2(*((const __half2*)(g + (size_t)node * 64 + lane * 2)));
    int e = e0;
    while (e1 - e >= 32) {
        int idx = srcs[e + lane];
#pragma unroll
        for (int k = 0; k < 32; k++) {
            int s = __shfl_sync(0xffffffffu, idx, k);
            float2 v = __half22float2(*((const __half2*)(g + (size_t)s * 64 + lane * 2)));
            acc.x += v.x; acc.y += v.y;
        }
        e += 32;
    }
    if (e < e1) {
        int m = e1 - e;
        int idx = (lane < m) ? srcs[e + lane] : 0;
#pragma unroll 8
        for (int k = 0; k < m; k++) {
            int s = __shfl_sync(0xffffffffu, idx, k);
            float2 v = __half22float2(*((const __half2*)(g + (size_t)s * 64 + lane * 2)));
            acc.x += v.x; acc.y += v.y;
        }
    }
    float dv = dinv[node];
    float2 bv = ((const float2*)bias)[lane];
    float2 r;
    r.x = acc.x * dv + bv.x;
    r.y = acc.y * dv + bv.y;
    ((float2*)(out + (size_t)node * 64))[lane] = r;
}

// ---------------- launch ----------------

extern "C" void kernel_launch(void* const* d_in, const int* in_sizes, int n_in,
                              void* d_out, int out_size) {
    const float* x   = (const float*)d_in[0];
    const int*   ei  = (const int*)d_in[1];    // int32 (JAX x64 disabled)
    const float* W1  = (const float*)d_in[2];
    const float* b1  = (const float*)d_in[3];
    const float* W2  = (const float*)d_in[4];
    const float* b2  = (const float*)d_in[5];
    float*       out = (float*)d_out;

    const int N = in_sizes[0] / 128;
    const int E = in_sizes[1] / 2;
    const int* srcp = ei;
    const int* dstp = ei + E;

    float*  dinv;  cudaGetSymbolAddress((void**)&dinv,  g_dinv);
    int*    count; cudaGetSymbolAddress((void**)&count, g_count);
    int*    rowst; cudaGetSymbolAddress((void**)&rowst, g_rowstart);
    int*    rank;  cudaGetSymbolAddress((void**)&rank,  g_rank);
    int*    bsum;  cudaGetSymbolAddress((void**)&bsum,  g_blocksum);
    int*    srcs;  cudaGetSymbolAddress((void**)&srcs,  g_srcs);
    __half* msg;   cudaGetSymbolAddress((void**)&msg,   g_msg);
    __half* h1h;   cudaGetSymbolAddress((void**)&h1h,   g_h1h);
    __half* msg2;  cudaGetSymbolAddress((void**)&msg2,  g_msg2);

    static cudaStream_t s2 = nullptr;
    static cudaEvent_t evRoot = nullptr, evG1 = nullptr, evA = nullptr, evB = nullptr;
    if (!s2) {
        cudaStreamCreateWithFlags(&s2, cudaStreamNonBlocking);
        cudaEventCreateWithFlags(&evRoot, cudaEventDisableTiming);
        cudaEventCreateWithFlags(&evG1, cudaEventDisableTiming);
        cudaEventCreateWithFlags(&evA, cudaEventDisableTiming);
        cudaEventCreateWithFlags(&evB, cudaEventDisableTiming);
    }

    const int T = 256;
    const int nb = (N + SCAN_B - 1) / SCAN_B;

    // node chunks for the gather1/GEMM2 pipeline (chunk0 multiple of BM=128)
    const int N0 = ((N / 2) / 128) * 128;        // 24960
    const int N1 = N - N0;

    // fork: GEMM1 (independent of CSR build — msg1 unscaled) on s2
    cudaEventRecord(evRoot, 0);
    cudaStreamWaitEvent(s2, evRoot, 0);
    k_gemm1_tc<<<(N + 127) / 128, 256, 0, s2>>>(x, W1, msg, N);
    cudaEventRecord(evG1, s2);

    // CSR build (stream 0)
    k_zero_int<<<(N + T - 1) / T, T>>>(count, N);
    k_hist<<<(E + T - 1) / T, T>>>(dstp, count, rank, E, N);
    k_scan1<<<nb, SCAN_B>>>(count, rowst, bsum, N);
    k_scan3<<<(N + T - 1) / T, T>>>(count, rowst, bsum, dinv, N, E, nb);
    k_fill<<<(E + T - 1) / T, T>>>(srcp, dstp, rowst, rank, srcs, E, N);

    // join: gather1 chunk0, then chunk1; GEMM2 chunk0 overlaps on s2
    cudaStreamWaitEvent(0, evG1, 0);
    k_gather128h<<<(N0 * 32 + T - 1) / T, T>>>(msg, rowst, srcs, dinv, b1, h1h, 0, N0);
    cudaEventRecord(evA, 0);
    k_gather128h<<<(N1 * 32 + T - 1) / T, T>>>(msg, rowst, srcs, dinv, b1, h1h, N0, N1);

    cudaStreamWaitEvent(s2, evA, 0);
    k_gemm2_tc<<<N0 / 128, 256, 0, s2>>>(h1h, W2, dinv, msg2, N0);
    cudaEventRecord(evB, s2);

    k_gemm2_tc<<<(N1 + 127) / 128, 256>>>(h1h + (size_t)N0 * 128, W2, dinv + N0,
                                          msg2 + (size_t)N0 * 64, N1);
    cudaStreamWaitEvent(0, evB, 0);
    k_gather64h<<<(N * 32 + T - 1) / T, T>>>(msg2, rowst, srcs, dinv, b2, out, N);
}

// round 11
// speedup vs baseline: 1.0436x; 1.0436x over previous
#include <cuda_runtime.h>
#include <cuda_fp16.h>
#include <cstdint>

// N=50000, E=1600000, F=128, H=128, C=64
#define NMAX 50000
#define EMAX 1600000
#define SCAN_B 1024

// Scratch (no dynamic allocation allowed)
__device__ __align__(16) float  g_dinv[NMAX];
__device__ __align__(16) int    g_count[NMAX];
__device__ __align__(16) int    g_rowstart[NMAX + 1];
__device__ __align__(16) int    g_rank[EMAX];
__device__ __align__(16) int    g_blocksum[(NMAX + SCAN_B - 1) / SCAN_B + 1];
__device__ __align__(16) int    g_srcs[EMAX];
__device__ __align__(16) __half g_msg [(size_t)NMAX * 128];  // msg1 = x@W1 (unscaled)
__device__ __align__(16) __half g_h1h [(size_t)NMAX * 128];  // h1 post-relu (fp16)
__device__ __align__(16) __half g_msg2[(size_t)NMAX * 64];   // msg2 = (h1@W2)*dinv

// ---------------- CSR build ----------------

__global__ void k_zero_int(int* p, int n) {
    int i = blockIdx.x * blockDim.x + threadIdx.x;
    if (i < n) p[i] = 0;
}

__global__ void k_hist(const int* __restrict__ dst, int* __restrict__ count,
                       int* __restrict__ rank, int E, int n) {
    int e = blockIdx.x * blockDim.x + threadIdx.x;
    if (e < E) {
        int d = dst[e];
        int r = 0;
        if ((unsigned)d < (unsigned)n) r = atomicAdd(&count[d], 1);
        rank[e] = r;
    }
}

__global__ void k_scan1(const int* __restrict__ count, int* __restrict__ rowstart,
                        int* __restrict__ blocksum, int n) {
    __shared__ int buf[SCAN_B];
    int i = blockIdx.x * SCAN_B + threadIdx.x;
    int v = (i < n) ? count[i] : 0;
    buf[threadIdx.x] = v;
    __syncthreads();
#pragma unroll
    for (int off = 1; off < SCAN_B; off <<= 1) {
        int t = 0;
        if ((int)threadIdx.x >= off) t = buf[threadIdx.x - off];
        __syncthreads();
        if ((int)threadIdx.x >= off) buf[threadIdx.x] += t;
        __syncthreads();
    }
    if (i < n) rowstart[i] = buf[threadIdx.x] - v;
    if (threadIdx.x == SCAN_B - 1) blocksum[blockIdx.x] = buf[SCAN_B - 1];
}

// scan3 with fused blocksum prefix (warp 0 re-derives the 49-entry exclusive scan)
__global__ void k_scan3(const int* __restrict__ count, int* __restrict__ rowstart,
                        const int* __restrict__ blocksum, float* __restrict__ dinv,
                        int n, int E, int nb) {
    __shared__ int pref[64];
    if (threadIdx.x < 32) {
        int lane = threadIdx.x;
        int carry = 0;
        for (int base = 0; base < nb; base += 32) {
            int i = base + lane;
            int v = (i < nb) ? blocksum[i] : 0;
            int x = v;
#pragma unroll
            for (int off = 1; off < 32; off <<= 1) {
                int t = __shfl_up_sync(0xffffffffu, x, off);
                if (lane >= off) x += t;
            }
            if (i < nb) pref[i] = carry + x - v;   // exclusive
            carry += __shfl_sync(0xffffffffu, x, 31);
        }
    }
    __syncthreads();
    int i = blockIdx.x * blockDim.x + threadIdx.x;
    if (i < n) {
        rowstart[i] += pref[i / SCAN_B];
        dinv[i] = rsqrtf((float)count[i] + 1.0f);
    }
    if (i == 0) rowstart[n] = E;
}

__global__ void k_fill(const int* __restrict__ src, const int* __restrict__ dst,
                       const int* __restrict__ rowstart, const int* __restrict__ rank,
                       int* __restrict__ srcs, int E, int n) {
    int e = blockIdx.x * blockDim.x + threadIdx.x;
    if (e < E) {
        int d = dst[e];
        int s = src[e];
        if ((unsigned)d < (unsigned)n && (unsigned)s < (unsigned)n)
            srcs[rowstart[d] + rank[e]] = s;
    }
}

// ---------------- tf32 tensor-core GEMMs ----------------

__device__ __forceinline__ uint32_t f2tf32(float f) {
    uint32_t u;
    asm("cvt.rna.tf32.f32 %0, %1;" : "=r"(u) : "f"(f));
    return u;
}

// fp32 input, OUTC=128, no dinv scaling (msg1 = x@W1)
__global__ void k_gemm1_tc(const float* __restrict__ X, const float* __restrict__ W,
                           __half* __restrict__ out, int N) {
    constexpr int OUTC = 128, BM = 128, BK = 32;
    constexpr int AP = 36, WP = OUTC + 4;
    constexpr int WARP_N = OUTC / 2, NNT = WARP_N / 8;
    __shared__ float As[BM * AP];
    __shared__ float Ws[BK * WP];

    const int tid  = threadIdx.x;
    const int warp = tid >> 5, lane = tid & 31;
    const int wm = warp >> 1, wn = warp & 1;
    const int g = lane >> 2, tig = lane & 3;
    const int rowBase = blockIdx.x * BM;

    float acc[2][NNT][4];
#pragma unroll
    for (int mt = 0; mt < 2; mt++)
#pragma unroll
        for (int nt = 0; nt < NNT; nt++)
#pragma unroll
            for (int c = 0; c < 4; c++) acc[mt][nt][c] = 0.f;

    for (int k0 = 0; k0 < 128; k0 += BK) {
#pragma unroll
        for (int j = 0; j < 4; j++) {
            int i4  = tid + j * 256;
            int row = i4 >> 3;
            int col = (i4 & 7) * 4;
            float4 v = make_float4(0.f, 0.f, 0.f, 0.f);
            if (rowBase + row < N)
                v = *((const float4*)(X + (size_t)(rowBase + row) * 128 + k0 + col));
            float* p = &As[row * AP + col];
            p[0] = __uint_as_float(f2tf32(v.x));
            p[1] = __uint_as_float(f2tf32(v.y));
            p[2] = __uint_as_float(f2tf32(v.z));
            p[3] = __uint_as_float(f2tf32(v.w));
        }
#pragma unroll
        for (int j = 0; j < 4; j++) {
            int i4  = tid + j * 256;
            int row = i4 >> 5;
            int col = (i4 & 31) * 4;
            float4 v = *((const float4*)(W + (size_t)(k0 + row) * OUTC + col));
            float* p = &Ws[row * WP + col];
            p[0] = __uint_as_float(f2tf32(v.x));
            p[1] = __uint_as_float(f2tf32(v.y));
            p[2] = __uint_as_float(f2tf32(v.z));
            p[3] = __uint_as_float(f2tf32(v.w));
        }
        __syncthreads();

#pragma unroll
        for (int kk = 0; kk < BK / 8; kk++) {
            int k = kk * 8;
            uint32_t a[2][4];
#pragma unroll
            for (int mt = 0; mt < 2; mt++) {
                int ar = wm * 32 + mt * 16;
                a[mt][0] = __float_as_uint(As[(ar + g)     * AP + k + tig]);
                a[mt][1] = __float_as_uint(As[(ar + g + 8) * AP + k + tig]);
                a[mt][2] = __float_as_uint(As[(ar + g)     * AP + k + tig + 4]);
                a[mt][3] = __float_as_uint(As[(ar + g + 8) * AP + k + tig + 4]);
            }
#pragma unroll
            for (int nt = 0; nt < NNT; nt++) {
                int nc = wn * WARP_N + nt * 8;
                uint32_t b0 = __float_as_uint(Ws[(k + tig)     * WP + nc + g]);
                uint32_t b1 = __float_as_uint(Ws[(k + tig + 4) * WP + nc + g]);
#pragma unroll
                for (int mt = 0; mt < 2; mt++) {
                    asm volatile(
                        "mma.sync.aligned.m16n8k8.row.col.f32.tf32.tf32.f32 "
                        "{%0,%1,%2,%3}, {%4,%5,%6,%7}, {%8,%9}, {%0,%1,%2,%3};"
                        : "+f"(acc[mt][nt][0]), "+f"(acc[mt][nt][1]),
                          "+f"(acc[mt][nt][2]), "+f"(acc[mt][nt][3])
                        : "r"(a[mt][0]), "r"(a[mt][1]), "r"(a[mt][2]), "r"(a[mt][3]),
                          "r"(b0), "r"(b1));
                }
            }
        }
        __syncthreads();
    }

#pragma unroll
    for (int mt = 0; mt < 2; mt++) {
        int r0 = rowBase + wm * 32 + mt * 16 + g;
        int r1 = r0 + 8;
#pragma unroll
        for (int nt = 0; nt < NNT; nt++) {
            int col = wn * WARP_N + nt * 8 + tig * 2;
            if (r0 < N)
                *((__half2*)(out + (size_t)r0 * OUTC + col)) =
                    __floats2half2_rn(acc[mt][nt][0], acc[mt][nt][1]);
            if (r1 < N)
                *((__half2*)(out + (size_t)r1 * OUTC + col)) =
                    __floats2half2_rn(acc[mt][nt][2], acc[mt][nt][3]);
        }
    }
}

// fp16 input, OUTC=64, dinv scaling (msg2 = (h1@W2)*dinv)
__global__ void k_gemm2_tc(const __half* __restrict__ Xh, const float* __restrict__ W,
                           const float* __restrict__ dinv, __half* __restrict__ out,
                           int Nrows) {
    constexpr int OUTC = 64, BM = 128, BK = 32;
    constexpr int AP = 36, WP = OUTC + 4;
    constexpr int WARP_N = OUTC / 2, NNT = WARP_N / 8;   // 32, 4
    __shared__ float As[BM * AP];
    __shared__ float Ws[BK * WP];

    const int tid  = threadIdx.x;
    const int warp = tid >> 5, lane = tid & 31;
    const int wm = warp >> 1, wn = warp & 1;
    const int g = lane >> 2, tig = lane & 3;
    const int rowBase = blockIdx.x * BM;

    float acc[2][NNT][4];
#pragma unroll
    for (int mt = 0; mt < 2; mt++)
#pragma unroll
        for (int nt = 0; nt < NNT; nt++)
#pragma unroll
            for (int c = 0; c < 4; c++) acc[mt][nt][c] = 0.f;

    for (int k0 = 0; k0 < 128; k0 += BK) {
        // A tile from fp16: 128 rows x 32 halves; uint4 = 8 halves; 512 uint4, 2/thread
#pragma unroll
        for (int j = 0; j < 2; j++) {
            int i4  = tid + j * 256;           // 0..511
            int row = i4 >> 2;
            int c8  = (i4 & 3) * 8;
            uint4 u = make_uint4(0, 0, 0, 0);
            if (rowBase + row < Nrows)
                u = *((const uint4*)(Xh + (size_t)(rowBase + row) * 128 + k0 + c8));
            const __half2* h2 = (const __half2*)&u;
            float* p = &As[row * AP + c8];
#pragma unroll
            for (int q = 0; q < 4; q++) {
                float2 f = __half22float2(h2[q]);
                p[q * 2 + 0] = __uint_as_float(f2tf32(f.x));
                p[q * 2 + 1] = __uint_as_float(f2tf32(f.y));
            }
        }
        // W tile: 32 rows x 64 floats = 512 float4, 2/thread
#pragma unroll
        for (int j = 0; j < 2; j++) {
            int i4  = tid + j * 256;
            int row = i4 >> 4;
            int col = (i4 & 15) * 4;
            float4 v = *((const float4*)(W + (size_t)(k0 + row) * OUTC + col));
            float* p = &Ws[row * WP + col];
            p[0] = __uint_as_float(f2tf32(v.x));
            p[1] = __uint_as_float(f2tf32(v.y));
            p[2] = __uint_as_float(f2tf32(v.z));
            p[3] = __uint_as_float(f2tf32(v.w));
        }
        __syncthreads();

#pragma unroll
        for (int kk = 0; kk < BK / 8; kk++) {
            int k = kk * 8;
            uint32_t a[2][4];
#pragma unroll
            for (int mt = 0; mt < 2; mt++) {
                int ar = wm * 32 + mt * 16;
                a[mt][0] = __float_as_uint(As[(ar + g)     * AP + k + tig]);
                a[mt][1] = __float_as_uint(As[(ar + g + 8) * AP + k + tig]);
                a[mt][2] = __float_as_uint(As[(ar + g)     * AP + k + tig + 4]);
                a[mt][3] = __float_as_uint(As[(ar + g + 8) * AP + k + tig + 4]);
            }
#pragma unroll
            for (int nt = 0; nt < NNT; nt++) {
                int nc = wn * WARP_N + nt * 8;
                uint32_t b0 = __float_as_uint(Ws[(k + tig)     * WP + nc + g]);
                uint32_t b1 = __float_as_uint(Ws[(k + tig + 4) * WP + nc + g]);
#pragma unroll
                for (int mt = 0; mt < 2; mt++) {
                    asm volatile(
                        "mma.sync.aligned.m16n8k8.row.col.f32.tf32.tf32.f32 "
                        "{%0,%1,%2,%3}, {%4,%5,%6,%7}, {%8,%9}, {%0,%1,%2,%3};"
                        : "+f"(acc[mt][nt][0]), "+f"(acc[mt][nt][1]),
                          "+f"(acc[mt][nt][2]), "+f"(acc[mt][nt][3])
                        : "r"(a[mt][0]), "r"(a[mt][1]), "r"(a[mt][2]), "r"(a[mt][3]),
                          "r"(b0), "r"(b1));
                }
            }
        }
        __syncthreads();
    }

#pragma unroll
    for (int mt = 0; mt < 2; mt++) {
        int r0 = rowBase + wm * 32 + mt * 16 + g;
        int r1 = r0 + 8;
        float dv0 = (r0 < Nrows) ? dinv[r0] : 0.f;
        float dv1 = (r1 < Nrows) ? dinv[r1] : 0.f;
#pragma unroll
        for (int nt = 0; nt < NNT; nt++) {
            int col = wn * WARP_N + nt * 8 + tig * 2;
            if (r0 < Nrows)
                *((__half2*)(out + (size_t)r0 * OUTC + col)) =
                    __floats2half2_rn(acc[mt][nt][0] * dv0, acc[mt][nt][1] * dv0);
            if (r1 < Nrows)
                *((__half2*)(out + (size_t)r1 * OUTC + col)) =
                    __floats2half2_rn(acc[mt][nt][2] * dv1, acc[mt][nt][3] * dv1);
        }
    }
}

// ---------------- gathers ----------------
// Layer 1: h1h = half(relu((Σ dinv[s]·msg[s] + dinv[n]·msg[n])·dinv[n] + b1))

__global__ void k_gather128h(const __half* __restrict__ g, const int* __restrict__ rowstart,
                             const int* __restrict__ srcs, const float* __restrict__ dinv,
                             const float* __restrict__ bias, __half* __restrict__ out, int n) {
    int node = (blockIdx.x * blockDim.x + threadIdx.x) >> 5;
    int lane = threadIdx.x & 31;
    if (node >= n) return;
    int e0 = rowstart[node], e1 = rowstart[node + 1];
    float dvn = dinv[node];

    float acc0, acc1, acc2, acc3;
    {
        uint2 u = *((const uint2*)(g + (size_t)node * 128 + lane * 4));
        float2 a = __half22float2(*(const __half2*)&u.x);
        float2 b = __half22float2(*(const __half2*)&u.y);
        acc0 = dvn * a.x; acc1 = dvn * a.y; acc2 = dvn * b.x; acc3 = dvn * b.y;
    }
    int e = e0;
    while (e1 - e >= 32) {
        int idx = srcs[e + lane];
        float dvl = dinv[idx];
#pragma unroll
        for (int k = 0; k < 32; k++) {
            int s    = __shfl_sync(0xffffffffu, idx, k);
            float ds = __shfl_sync(0xffffffffu, dvl, k);
            uint2 u = *((const uint2*)(g + (size_t)s * 128 + lane * 4));
            float2 a = __half22float2(*(const __half2*)&u.x);
            float2 b = __half22float2(*(const __half2*)&u.y);
            acc0 += ds * a.x; acc1 += ds * a.y; acc2 += ds * b.x; acc3 += ds * b.y;
        }
        e += 32;
    }
    if (e < e1) {
        int m = e1 - e;
        int idx = (lane < m) ? srcs[e + lane] : 0;
        float dvl = (lane < m) ? dinv[idx] : 0.f;
#pragma unroll 8
        for (int k = 0; k < m; k++) {
            int s    = __shfl_sync(0xffffffffu, idx, k);
            float ds = __shfl_sync(0xffffffffu, dvl, k);
            uint2 u = *((const uint2*)(g + (size_t)s * 128 + lane * 4));
            float2 a = __half22float2(*(const __half2*)&u.x);
            float2 b = __half22float2(*(const __half2*)&u.y);
            acc0 += ds * a.x; acc1 += ds * a.y; acc2 += ds * b.x; acc3 += ds * b.y;
        }
    }
    float4 bv = ((const float4*)bias)[lane];
    __half2 h01 = __floats2half2_rn(fmaxf(acc0 * dvn + bv.x, 0.f),
                                    fmaxf(acc1 * dvn + bv.y, 0.f));
    __half2 h23 = __floats2half2_rn(fmaxf(acc2 * dvn + bv.z, 0.f),
                                    fmaxf(acc3 * dvn + bv.w, 0.f));
    uint2 st;
    st.x = *(const uint32_t*)&h01;
    st.y = *(const uint32_t*)&h23;
    *((uint2*)(out + (size_t)node * 128 + lane * 4)) = st;
}

// Layer 2: out = (Σ msg2[s] + msg2[n])·dinv[n] + b2   (msg2 already dinv-scaled)
__global__ void k_gather64h(const __half* __restrict__ g, const int* __restrict__ rowstart,
                            const int* __restrict__ srcs, const float* __restrict__ dinv,
                            const float* __restrict__ bias, float* __restrict__ out, int n) {
    int node = (blockIdx.x * blockDim.x + threadIdx.x) >> 5;
    int lane = threadIdx.x & 31;
    if (node >= n) return;
    int e0 = rowstart[node], e1 = rowstart[node + 1];

    float2 acc = __half22float2(*((const __half2*)(g + (size_t)node * 64 + lane * 2)));
    int e = e0;
    while (e1 - e >= 32) {
        int idx = srcs[e + lane];
#pragma unroll
        for (int k = 0; k < 32; k++) {
            int s = __shfl_sync(0xffffffffu, idx, k);
            float2 v = __half22float2(*((const __half2*)(g + (size_t)s * 64 + lane * 2)));
            acc.x += v.x; acc.y += v.y;
        }
        e += 32;
    }
    if (e < e1) {
        int m = e1 - e;
        int idx = (lane < m) ? srcs[e + lane] : 0;
#pragma unroll 8
        for (int k = 0; k < m; k++) {
            int s = __shfl_sync(0xffffffffu, idx, k);
            float2 v = __half22float2(*((const __half2*)(g + (size_t)s * 64 + lane * 2)));
            acc.x += v.x; acc.y += v.y;
        }
    }
    float dv = dinv[node];
    float2 bv = ((const float2*)bias)[lane];
    float2 r;
    r.x = acc.x * dv + bv.x;
    r.y = acc.y * dv + bv.y;
    ((float2*)(out + (size_t)node * 64))[lane] = r;
}

// ---------------- launch ----------------

extern "C" void kernel_launch(void* const* d_in, const int* in_sizes, int n_in,
                              void* d_out, int out_size) {
    const float* x   = (const float*)d_in[0];
    const int*   ei  = (const int*)d_in[1];    // int32 (JAX x64 disabled)
    const float* W1  = (const float*)d_in[2];
    const float* b1  = (const float*)d_in[3];
    const float* W2  = (const float*)d_in[4];
    const float* b2  = (const float*)d_in[5];
    float*       out = (float*)d_out;

    const int N = in_sizes[0] / 128;
    const int E = in_sizes[1] / 2;
    const int* srcp = ei;
    const int* dstp = ei + E;

    float*  dinv;  cudaGetSymbolAddress((void**)&dinv,  g_dinv);
    int*    count; cudaGetSymbolAddress((void**)&count, g_count);
    int*    rowst; cudaGetSymbolAddress((void**)&rowst, g_rowstart);
    int*    rank;  cudaGetSymbolAddress((void**)&rank,  g_rank);
    int*    bsum;  cudaGetSymbolAddress((void**)&bsum,  g_blocksum);
    int*    srcs;  cudaGetSymbolAddress((void**)&srcs,  g_srcs);
    __half* msg;   cudaGetSymbolAddress((void**)&msg,   g_msg);
    __half* h1h;   cudaGetSymbolAddress((void**)&h1h,   g_h1h);
    __half* msg2;  cudaGetSymbolAddress((void**)&msg2,  g_msg2);

    static cudaStream_t s2 = nullptr;
    static cudaEvent_t evRoot = nullptr, evG1 = nullptr;
    if (!s2) {
        cudaStreamCreateWithFlags(&s2, cudaStreamNonBlocking);
        cudaEventCreateWithFlags(&evRoot, cudaEventDisableTiming);
        cudaEventCreateWithFlags(&evG1, cudaEventDisableTiming);
    }

    const int T = 256;
    const int nb = (N + SCAN_B - 1) / SCAN_B;

    // fork: GEMM1 (independent of CSR build — msg1 unscaled) on s2
    cudaEventRecord(evRoot, 0);
    cudaStreamWaitEvent(s2, evRoot, 0);
    k_gemm1_tc<<<(N + 127) / 128, 256, 0, s2>>>(x, W1, msg, N);
    cudaEventRecord(evG1, s2);

    // CSR build (stream 0)
    k_zero_int<<<(N + T - 1) / T, T>>>(count, N);
    k_hist<<<(E + T - 1) / T, T>>>(dstp, count, rank, E, N);
    k_scan1<<<nb, SCAN_B>>>(count, rowst, bsum, N);
    k_scan3<<<(N + T - 1) / T, T>>>(count, rowst, bsum, dinv, N, E, nb);
    k_fill<<<(E + T - 1) / T, T>>>(srcp, dstp, rowst, rank, srcs, E, N);

    // join: gather1 needs CSR + GEMM1
    cudaStreamWaitEvent(0, evG1, 0);
    k_gather128h<<<(N * 32 + T - 1) / T, T>>>(msg, rowst, srcs, dinv, b1, h1h, N);

    // layer 2
    k_gemm2_tc<<<(N + 127) / 128, 256>>>(h1h, W2, dinv, msg2, N);
    k_gather64h<<<(N * 32 + T - 1) / T, T>>>(msg2, rowst, srcs, dinv, b2, out, N);
}

// round 12
// speedup vs baseline: 1.0480x; 1.0043x over previous
#include <cuda_runtime.h>
#include <cuda_fp16.h>
#include <cstdint>

// N=50000, E=1600000, F=128, H=128, C=64
#define NMAX 50000
#define EMAX 1600000
#define SCAN_B 1024
#define NB_MAX 64

// Scratch (no dynamic allocation allowed)
__device__ __align__(16) float  g_dinv[NMAX];
__device__ __align__(16) int    g_count[NMAX];
__device__ __align__(16) int    g_rowstart[NMAX + 1];
__device__ __align__(16) int    g_rank[EMAX];
__device__ __align__(16) unsigned long long g_lbstate[NB_MAX];  // decoupled-lookback state
__device__ __align__(16) int    g_srcs[EMAX];
__device__ __align__(16) __half g_msg [(size_t)NMAX * 128];  // msg1 = x@W1 (unscaled)
__device__ __align__(16) __half g_h1h [(size_t)NMAX * 128];  // h1 post-relu (fp16)
__device__ __align__(16) __half g_msg2[(size_t)NMAX * 64];   // msg2 = (h1@W2)*dinv

// ---------------- CSR build ----------------

__global__ void k_zero2(int* a, int na, int* b, int nb) {
    int i = blockIdx.x * blockDim.x + threadIdx.x;
    if (i < na) a[i] = 0;
    if (i < nb) b[i] = 0;
}

// 4 edges per thread
__global__ void k_hist4(const int* __restrict__ dst, int* __restrict__ count,
                        int* __restrict__ rank, int E, int n) {
    int i = blockIdx.x * blockDim.x + threadIdx.x;
    int e = i * 4;
    if (e + 3 < E) {
        int4 d = *((const int4*)(dst + e));
        int4 r;
        r.x = ((unsigned)d.x < (unsigned)n) ? atomicAdd(&count[d.x], 1) : 0;
        r.y = ((unsigned)d.y < (unsigned)n) ? atomicAdd(&count[d.y], 1) : 0;
        r.z = ((unsigned)d.z < (unsigned)n) ? atomicAdd(&count[d.z], 1) : 0;
        r.w = ((unsigned)d.w < (unsigned)n) ? atomicAdd(&count[d.w], 1) : 0;
        *((int4*)(rank + e)) = r;
    } else if (e < E) {
        for (; e < E; e++) {
            int d = dst[e];
            rank[e] = ((unsigned)d < (unsigned)n) ? atomicAdd(&count[d], 1) : 0;
        }
    }
}

__device__ __forceinline__ unsigned long long ldv_u64(const unsigned long long* p) {
    unsigned long long v;
    asm volatile("ld.volatile.global.u64 %0, [%1];" : "=l"(v) : "l"(p));
    return v;
}

// Fused exclusive scan (decoupled lookback) + dinv + rowstart[n]=E. One launch.
__global__ void k_scan_lb(const int* __restrict__ count, int* __restrict__ rowstart,
                          float* __restrict__ dinv, unsigned long long* __restrict__ state,
                          int n, int E) {
    __shared__ int wsum[32], wpre[32];
    __shared__ int prefix_s;
    const int tid = threadIdx.x;
    const int lane = tid & 31, wid = tid >> 5;
    const int b = blockIdx.x;
    const int i = b * SCAN_B + tid;
    int v = (i < n) ? count[i] : 0;

    // warp-level inclusive scan
    int x = v;
#pragma unroll
    for (int off = 1; off < 32; off <<= 1) {
        int t = __shfl_up_sync(0xffffffffu, x, off);
        if (lane >= off) x += t;
    }
    if (lane == 31) wsum[wid] = x;
    __syncthreads();

    if (wid == 0) {
        // scan the 32 warp sums
        int s = wsum[lane];
        int y = s;
#pragma unroll
        for (int off = 1; off < 32; off <<= 1) {
            int t = __shfl_up_sync(0xffffffffu, y, off);
            if (lane >= off) y += t;
        }
        wpre[lane] = y - s;                      // exclusive warp prefix
        int total = __shfl_sync(0xffffffffu, y, 31);

        // publish aggregate
        if (lane == 0)
            atomicExch(&state[b], (1ull << 32) | (unsigned)total);

        // lookback (32-wide windows)
        int prefix = 0;
        if (b > 0) {
            int base = b;
            while (true) {
                int p = base - 1 - lane;         // lane 0 = nearest predecessor
                int fl = 2, val = 0;
                if (p >= 0) {
                    unsigned long long s64;
                    do { s64 = ldv_u64(&state[p]); fl = (int)(s64 >> 32); } while (fl == 0);
                    val = (int)(unsigned)s64;
                }
                unsigned m2 = __ballot_sync(0xffffffffu, fl == 2);
                if (m2) {
                    int firstLane = __ffs(m2) - 1;  // closest predecessor with full prefix
                    prefix += __reduce_add_sync(0xffffffffu, (lane <= firstLane) ? val : 0);
                    break;
                } else {
                    prefix += __reduce_add_sync(0xffffffffu, val);
                    base -= 32;
                }
            }
        }
        if (lane == 0) {
            atomicExch(&state[b], (2ull << 32) | (unsigned)(prefix + total));
            prefix_s = prefix;
        }
    }
    __syncthreads();

    int incl = x + wpre[wid];
    if (i < n) {
        rowstart[i] = incl - v + prefix_s;       // global exclusive
        dinv[i] = rsqrtf((float)v + 1.0f);
    }
    if (b == gridDim.x - 1 && tid == 0) rowstart[n] = E;
}

// 4 edges per thread, atomic-free via rank
__global__ void k_fill4(const int* __restrict__ src, const int* __restrict__ dst,
                        const int* __restrict__ rowstart, const int* __restrict__ rank,
                        int* __restrict__ srcs, int E, int n) {
    int i = blockIdx.x * blockDim.x + threadIdx.x;
    int e = i * 4;
    if (e + 3 < E) {
        int4 s4 = *((const int4*)(src + e));
        int4 d4 = *((const int4*)(dst + e));
        int4 r4 = *((const int4*)(rank + e));
        if ((unsigned)d4.x < (unsigned)n && (unsigned)s4.x < (unsigned)n) srcs[rowstart[d4.x] + r4.x] = s4.x;
        if ((unsigned)d4.y < (unsigned)n && (unsigned)s4.y < (unsigned)n) srcs[rowstart[d4.y] + r4.y] = s4.y;
        if ((unsigned)d4.z < (unsigned)n && (unsigned)s4.z < (unsigned)n) srcs[rowstart[d4.z] + r4.z] = s4.z;
        if ((unsigned)d4.w < (unsigned)n && (unsigned)s4.w < (unsigned)n) srcs[rowstart[d4.w] + r4.w] = s4.w;
    } else if (e < E) {
        for (; e < E; e++) {
            int d = dst[e], s = src[e];
            if ((unsigned)d < (unsigned)n && (unsigned)s < (unsigned)n)
                srcs[rowstart[d] + rank[e]] = s;
        }
    }
}

// ---------------- tf32 tensor-core GEMMs ----------------

__device__ __forceinline__ uint32_t f2tf32(float f) {
    uint32_t u;
    asm("cvt.rna.tf32.f32 %0, %1;" : "=r"(u) : "f"(f));
    return u;
}

// fp32 input, OUTC=128, no dinv scaling (msg1 = x@W1)
__global__ void k_gemm1_tc(const float* __restrict__ X, const float* __restrict__ W,
                           __half* __restrict__ out, int N) {
    constexpr int OUTC = 128, BM = 128, BK = 32;
    constexpr int AP = 36, WP = OUTC + 4;
    constexpr int WARP_N = OUTC / 2, NNT = WARP_N / 8;
    __shared__ float As[BM * AP];
    __shared__ float Ws[BK * WP];

    const int tid  = threadIdx.x;
    const int warp = tid >> 5, lane = tid & 31;
    const int wm = warp >> 1, wn = warp & 1;
    const int g = lane >> 2, tig = lane & 3;
    const int rowBase = blockIdx.x * BM;

    float acc[2][NNT][4];
#pragma unroll
    for (int mt = 0; mt < 2; mt++)
#pragma unroll
        for (int nt = 0; nt < NNT; nt++)
#pragma unroll
            for (int c = 0; c < 4; c++) acc[mt][nt][c] = 0.f;

    for (int k0 = 0; k0 < 128; k0 += BK) {
#pragma unroll
        for (int j = 0; j < 4; j++) {
            int i4  = tid + j * 256;
            int row = i4 >> 3;
            int col = (i4 & 7) * 4;
            float4 v = make_float4(0.f, 0.f, 0.f, 0.f);
            if (rowBase + row < N)
                v = *((const float4*)(X + (size_t)(rowBase + row) * 128 + k0 + col));
            float* p = &As[row * AP + col];
            p[0] = __uint_as_float(f2tf32(v.x));
            p[1] = __uint_as_float(f2tf32(v.y));
            p[2] = __uint_as_float(f2tf32(v.z));
            p[3] = __uint_as_float(f2tf32(v.w));
        }
#pragma unroll
        for (int j = 0; j < 4; j++) {
            int i4  = tid + j * 256;
            int row = i4 >> 5;
            int col = (i4 & 31) * 4;
            float4 v = *((const float4*)(W + (size_t)(k0 + row) * OUTC + col));
            float* p = &Ws[row * WP + col];
            p[0] = __uint_as_float(f2tf32(v.x));
            p[1] = __uint_as_float(f2tf32(v.y));
            p[2] = __uint_as_float(f2tf32(v.z));
            p[3] = __uint_as_float(f2tf32(v.w));
        }
        __syncthreads();

#pragma unroll
        for (int kk = 0; kk < BK / 8; kk++) {
            int k = kk * 8;
            uint32_t a[2][4];
#pragma unroll
            for (int mt = 0; mt < 2; mt++) {
                int ar = wm * 32 + mt * 16;
                a[mt][0] = __float_as_uint(As[(ar + g)     * AP + k + tig]);
                a[mt][1] = __float_as_uint(As[(ar + g + 8) * AP + k + tig]);
                a[mt][2] = __float_as_uint(As[(ar + g)     * AP + k + tig + 4]);
                a[mt][3] = __float_as_uint(As[(ar + g + 8) * AP + k + tig + 4]);
            }
#pragma unroll
            for (int nt = 0; nt < NNT; nt++) {
                int nc = wn * WARP_N + nt * 8;
                uint32_t b0 = __float_as_uint(Ws[(k + tig)     * WP + nc + g]);
                uint32_t b1 = __float_as_uint(Ws[(k + tig + 4) * WP + nc + g]);
#pragma unroll
                for (int mt = 0; mt < 2; mt++) {
                    asm volatile(
                        "mma.sync.aligned.m16n8k8.row.col.f32.tf32.tf32.f32 "
                        "{%0,%1,%2,%3}, {%4,%5,%6,%7}, {%8,%9}, {%0,%1,%2,%3};"
                        : "+f"(acc[mt][nt][0]), "+f"(acc[mt][nt][1]),
                          "+f"(acc[mt][nt][2]), "+f"(acc[mt][nt][3])
                        : "r"(a[mt][0]), "r"(a[mt][1]), "r"(a[mt][2]), "r"(a[mt][3]),
                          "r"(b0), "r"(b1));
                }
            }
        }
        __syncthreads();
    }

#pragma unroll
    for (int mt = 0; mt < 2; mt++) {
        int r0 = rowBase + wm * 32 + mt * 16 + g;
        int r1 = r0 + 8;
#pragma unroll
        for (int nt = 0; nt < NNT; nt++) {
            int col = wn * WARP_N + nt * 8 + tig * 2;
            if (r0 < N)
                *((__half2*)(out + (size_t)r0 * OUTC + col)) =
                    __floats2half2_rn(acc[mt][nt][0], acc[mt][nt][1]);
            if (r1 < N)
                *((__half2*)(out + (size_t)r1 * OUTC + col)) =
                    __floats2half2_rn(acc[mt][nt][2], acc[mt][nt][3]);
        }
    }
}

// fp16 input, OUTC=64, dinv scaling (msg2 = (h1@W2)*dinv)
__global__ void k_gemm2_tc(const __half* __restrict__ Xh, const float* __restrict__ W,
                           const float* __restrict__ dinv, __half* __restrict__ out,
                           int Nrows) {
    constexpr int OUTC = 64, BM = 128, BK = 32;
    constexpr int AP = 36, WP = OUTC + 4;
    constexpr int WARP_N = OUTC / 2, NNT = WARP_N / 8;   // 32, 4
    __shared__ float As[BM * AP];
    __shared__ float Ws[BK * WP];

    const int tid  = threadIdx.x;
    const int warp = tid >> 5, lane = tid & 31;
    const int wm = warp >> 1, wn = warp & 1;
    const int g = lane >> 2, tig = lane & 3;
    const int rowBase = blockIdx.x * BM;

    float acc[2][NNT][4];
#pragma unroll
    for (int mt = 0; mt < 2; mt++)
#pragma unroll
        for (int nt = 0; nt < NNT; nt++)
#pragma unroll
            for (int c = 0; c < 4; c++) acc[mt][nt][c] = 0.f;

    for (int k0 = 0; k0 < 128; k0 += BK) {
#pragma unroll
        for (int j = 0; j < 2; j++) {
            int i4  = tid + j * 256;           // 0..511
            int row = i4 >> 2;
            int c8  = (i4 & 3) * 8;
            uint4 u = make_uint4(0, 0, 0, 0);
            if (rowBase + row < Nrows)
                u = *((const uint4*)(Xh + (size_t)(rowBase + row) * 128 + k0 + c8));
            const __half2* h2 = (const __half2*)&u;
            float* p = &As[row * AP + c8];
#pragma unroll
            for (int q = 0; q < 4; q++) {
                float2 f = __half22float2(h2[q]);
                p[q * 2 + 0] = __uint_as_float(f2tf32(f.x));
                p[q * 2 + 1] = __uint_as_float(f2tf32(f.y));
            }
        }
#pragma unroll
        for (int j = 0; j < 2; j++) {
            int i4  = tid + j * 256;
            int row = i4 >> 4;
            int col = (i4 & 15) * 4;
            float4 v = *((const float4*)(W + (size_t)(k0 + row) * OUTC + col));
            float* p = &Ws[row * WP + col];
            p[0] = __uint_as_float(f2tf32(v.x));
            p[1] = __uint_as_float(f2tf32(v.y));
            p[2] = __uint_as_float(f2tf32(v.z));
            p[3] = __uint_as_float(f2tf32(v.w));
        }
        __syncthreads();

#pragma unroll
        for (int kk = 0; kk < BK / 8; kk++) {
            int k = kk * 8;
            uint32_t a[2][4];
#pragma unroll
            for (int mt = 0; mt < 2; mt++) {
                int ar = wm * 32 + mt * 16;
                a[mt][0] = __float_as_uint(As[(ar + g)     * AP + k + tig]);
                a[mt][1] = __float_as_uint(As[(ar + g + 8) * AP + k + tig]);
                a[mt][2] = __float_as_uint(As[(ar + g)     * AP + k + tig + 4]);
                a[mt][3] = __float_as_uint(As[(ar + g + 8) * AP + k + tig + 4]);
            }
#pragma unroll
            for (int nt = 0; nt < NNT; nt++) {
                int nc = wn * WARP_N + nt * 8;
                uint32_t b0 = __float_as_uint(Ws[(k + tig)     * WP + nc + g]);
                uint32_t b1 = __float_as_uint(Ws[(k + tig + 4) * WP + nc + g]);
#pragma unroll
                for (int mt = 0; mt < 2; mt++) {
                    asm volatile(
                        "mma.sync.aligned.m16n8k8.row.col.f32.tf32.tf32.f32 "
                        "{%0,%1,%2,%3}, {%4,%5,%6,%7}, {%8,%9}, {%0,%1,%2,%3};"
                        : "+f"(acc[mt][nt][0]), "+f"(acc[mt][nt][1]),
                          "+f"(acc[mt][nt][2]), "+f"(acc[mt][nt][3])
                        : "r"(a[mt][0]), "r"(a[mt][1]), "r"(a[mt][2]), "r"(a[mt][3]),
                          "r"(b0), "r"(b1));
                }
            }
        }
        __syncthreads();
    }

#pragma unroll
    for (int mt = 0; mt < 2; mt++) {
        int r0 = rowBase + wm * 32 + mt * 16 + g;
        int r1 = r0 + 8;
        float dv0 = (r0 < Nrows) ? dinv[r0] : 0.f;
        float dv1 = (r1 < Nrows) ? dinv[r1] : 0.f;
#pragma unroll
        for (int nt = 0; nt < NNT; nt++) {
            int col = wn * WARP_N + nt * 8 + tig * 2;
            if (r0 < Nrows)
                *((__half2*)(out + (size_t)r0 * OUTC + col)) =
                    __floats2half2_rn(acc[mt][nt][0] * dv0, acc[mt][nt][1] * dv0);
            if (r1 < Nrows)
                *((__half2*)(out + (size_t)r1 * OUTC + col)) =
                    __floats2half2_rn(acc[mt][nt][2] * dv1, acc[mt][nt][3] * dv1);
        }
    }
}

// ---------------- gathers ----------------
// Layer 1: h1h = half(relu((Σ dinv[s]·msg[s] + dinv[n]·msg[n])·dinv[n] + b1))

__global__ void k_gather128h(const __half* __restrict__ g, const int* __restrict__ rowstart,
                             const int* __restrict__ srcs, const float* __restrict__ dinv,
                             const float* __restrict__ bias, __half* __restrict__ out, int n) {
    int node = (blockIdx.x * blockDim.x + threadIdx.x) >> 5;
    int lane = threadIdx.x & 31;
    if (node >= n) return;
    int e0 = rowstart[node], e1 = rowstart[node + 1];
    float dvn = dinv[node];

    float acc0, acc1, acc2, acc3;
    {
        uint2 u = *((const uint2*)(g + (size_t)node * 128 + lane * 4));
        float2 a = __half22float2(*(const __half2*)&u.x);
        float2 b = __half22float2(*(const __half2*)&u.y);
        acc0 = dvn * a.x; acc1 = dvn * a.y; acc2 = dvn * b.x; acc3 = dvn * b.y;
    }
    int e = e0;
    while (e1 - e >= 32) {
        int idx = srcs[e + lane];
        float dvl = dinv[idx];
#pragma unroll
        for (int k = 0; k < 32; k++) {
            int s    = __shfl_sync(0xffffffffu, idx, k);
            float ds = __shfl_sync(0xffffffffu, dvl, k);
            uint2 u = *((const uint2*)(g + (size_t)s * 128 + lane * 4));
            float2 a = __half22float2(*(const __half2*)&u.x);
            float2 b = __half22float2(*(const __half2*)&u.y);
            acc0 += ds * a.x; acc1 += ds * a.y; acc2 += ds * b.x; acc3 += ds * b.y;
        }
        e += 32;
    }
    if (e < e1) {
        int m = e1 - e;
        int idx = (lane < m) ? srcs[e + lane] : 0;
        float dvl = (lane < m) ? dinv[idx] : 0.f;
#pragma unroll 8
        for (int k = 0; k < m; k++) {
            int s    = __shfl_sync(0xffffffffu, idx, k);
            float ds = __shfl_sync(0xffffffffu, dvl, k);
            uint2 u = *((const uint2*)(g + (size_t)s * 128 + lane * 4));
            float2 a = __half22float2(*(const __half2*)&u.x);
            float2 b = __half22float2(*(const __half2*)&u.y);
            acc0 += ds * a.x; acc1 += ds * a.y; acc2 += ds * b.x; acc3 += ds * b.y;
        }
    }
    float4 bv = ((const float4*)bias)[lane];
    __half2 h01 = __floats2half2_rn(fmaxf(acc0 * dvn + bv.x, 0.f),
                                    fmaxf(acc1 * dvn + bv.y, 0.f));
    __half2 h23 = __floats2half2_rn(fmaxf(acc2 * dvn + bv.z, 0.f),
                                    fmaxf(acc3 * dvn + bv.w, 0.f));
    uint2 st;
    st.x = *(const uint32_t*)&h01;
    st.y = *(const uint32_t*)&h23;
    *((uint2*)(out + (size_t)node * 128 + lane * 4)) = st;
}

// Layer 2: out = (Σ msg2[s] + msg2[n])·dinv[n] + b2   (msg2 already dinv-scaled)
__global__ void k_gather64h(const __half* __restrict__ g, const int* __restrict__ rowstart,
                            const int* __restrict__ srcs, const float* __restrict__ dinv,
                            const float* __restrict__ bias, float* __restrict__ out, int n) {
    int node = (blockIdx.x * blockDim.x + threadIdx.x) >> 5;
    int lane = threadIdx.x & 31;
    if (node >= n) return;
    int e0 = rowstart[node], e1 = rowstart[node + 1];

    float2 acc = __half22float2(*((const __half2*)(g + (size_t)node * 64 + lane * 2)));
    int e = e0;
    while (e1 - e >= 32) {
        int idx = srcs[e + lane];
#pragma unroll
        for (int k = 0; k < 32; k++) {
            int s = __shfl_sync(0xffffffffu, idx, k);
            float2 v = __half22float2(*((const __half2*)(g + (size_t)s * 64 + lane * 2)));
            acc.x += v.x; acc.y += v.y;
        }
        e += 32;
    }
    if (e < e1) {
        int m = e1 - e;
        int idx = (lane < m) ? srcs[e + lane] : 0;
#pragma unroll 8
        for (int k = 0; k < m; k++) {
            int s = __shfl_sync(0xffffffffu, idx, k);
            float2 v = __half22float2(*((const __half2*)(g + (size_t)s * 64 + lane * 2)));
            acc.x += v.x; acc.y += v.y;
        }
    }
    float dv = dinv[node];
    float2 bv = ((const float2*)bias)[lane];
    float2 r;
    r.x = acc.x * dv + bv.x;
    r.y = acc.y * dv + bv.y;
    ((float2*)(out + (size_t)node * 64))[lane] = r;
}

// ---------------- launch ----------------

extern "C" void kernel_launch(void* const* d_in, const int* in_sizes, int n_in,
                              void* d_out, int out_size) {
    const float* x   = (const float*)d_in[0];
    const int*   ei  = (const int*)d_in[1];    // int32 (JAX x64 disabled)
    const float* W1  = (const float*)d_in[2];
    const float* b1  = (const float*)d_in[3];
    const float* W2  = (const float*)d_in[4];
    const float* b2  = (const float*)d_in[5];
    float*       out = (float*)d_out;

    const int N = in_sizes[0] / 128;
    const int E = in_sizes[1] / 2;
    const int* srcp = ei;
    const int* dstp = ei + E;

    float*  dinv;  cudaGetSymbolAddress((void**)&dinv,  g_dinv);
    int*    count; cudaGetSymbolAddress((void**)&count, g_count);
    int*    rowst; cudaGetSymbolAddress((void**)&rowst, g_rowstart);
    int*    rank;  cudaGetSymbolAddress((void**)&rank,  g_rank);
    unsigned long long* lbst; cudaGetSymbolAddress((void**)&lbst, g_lbstate);
    int*    srcs;  cudaGetSymbolAddress((void**)&srcs,  g_srcs);
    __half* msg;   cudaGetSymbolAddress((void**)&msg,   g_msg);
    __half* h1h;   cudaGetSymbolAddress((void**)&h1h,   g_h1h);
    __half* msg2;  cudaGetSymbolAddress((void**)&msg2,  g_msg2);

    static cudaStream_t s2 = nullptr;
    static cudaEvent_t evRoot = nullptr, evG1 = nullptr;
    if (!s2) {
        cudaStreamCreateWithFlags(&s2, cudaStreamNonBlocking);
        cudaEventCreateWithFlags(&evRoot, cudaEventDisableTiming);
        cudaEventCreateWithFlags(&evG1, cudaEventDisableTiming);
    }

    const int T = 256;
    const int nb = (N + SCAN_B - 1) / SCAN_B;   // 49

    // fork: GEMM1 (independent of CSR build — msg1 unscaled) on s2
    cudaEventRecord(evRoot, 0);
    cudaStreamWaitEvent(s2, evRoot, 0);
    k_gemm1_tc<<<(N + 127) / 128, 256, 0, s2>>>(x, W1, msg, N);
    cudaEventRecord(evG1, s2);

    // CSR build (stream 0)
    k_zero2<<<(N + T - 1) / T, T>>>(count, N, (int*)lbst, NB_MAX * 2);
    k_hist4<<<(E / 4 + T) / T, T>>>(dstp, count, rank, E, N);
    k_scan_lb<<<nb, SCAN_B>>>(count, rowst, dinv, lbst, N, E);
    k_fill4<<<(E / 4 + T) / T, T>>>(srcp, dstp, rowst, rank, srcs, E, N);

    // join: gather1 needs CSR + GEMM1
    cudaStreamWaitEvent(0, evG1, 0);
    k_gather128h<<<(N * 32 + T - 1) / T, T>>>(msg, rowst, srcs, dinv, b1, h1h, N);

    // layer 2
    k_gemm2_tc<<<(N + 127) / 128, 256>>>(h1h, W2, dinv, msg2, N);
    k_gather64h<<<(N * 32 + T - 1) / T, T>>>(msg2, rowst, srcs, dinv, b2, out, N);
}

// round 13
// speedup vs baseline: 1.0894x; 1.0395x over previous
#include <cuda_runtime.h>
#include <cuda_fp16.h>
#include <cstdint>

// N=50000, E=1600000, F=128, H=128, C=64
#define NMAX 50000
#define EMAX 1600000
#define SCAN_B 1024
#define NB_MAX 64

// Scratch (no dynamic allocation allowed)
__device__ __align__(16) float  g_dinv[NMAX];
__device__ __align__(16) int    g_count[NMAX];
__device__ __align__(16) int    g_rowstart[NMAX + 1];
__device__ __align__(16) int    g_rank[EMAX];
__device__ __align__(16) unsigned long long g_lbstate[NB_MAX];
__device__ __align__(16) int    g_srcs[EMAX];
__device__ __align__(16) __half g_msg [(size_t)NMAX * 128];  // msg1 = (x@W1)*dinv (pre-scaled)
__device__ __align__(16) __half g_h1h [(size_t)NMAX * 128];  // h1 post-relu (fp16)
__device__ __align__(16) __half g_msg2[(size_t)NMAX * 64];   // msg2 = (h1@W2)*dinv

// ---------------- CSR build ----------------

__global__ void k_zero2(int* a, int na, int* b, int nb) {
    int i = blockIdx.x * blockDim.x + threadIdx.x;
    if (i < na) a[i] = 0;
    if (i < nb) b[i] = 0;
}

// 4 edges per thread
__global__ void k_hist4(const int* __restrict__ dst, int* __restrict__ count,
                        int* __restrict__ rank, int E, int n) {
    int i = blockIdx.x * blockDim.x + threadIdx.x;
    int e = i * 4;
    if (e + 3 < E) {
        int4 d = *((const int4*)(dst + e));
        int4 r;
        r.x = ((unsigned)d.x < (unsigned)n) ? atomicAdd(&count[d.x], 1) : 0;
        r.y = ((unsigned)d.y < (unsigned)n) ? atomicAdd(&count[d.y], 1) : 0;
        r.z = ((unsigned)d.z < (unsigned)n) ? atomicAdd(&count[d.z], 1) : 0;
        r.w = ((unsigned)d.w < (unsigned)n) ? atomicAdd(&count[d.w], 1) : 0;
        *((int4*)(rank + e)) = r;
    } else if (e < E) {
        for (; e < E; e++) {
            int d = dst[e];
            rank[e] = ((unsigned)d < (unsigned)n) ? atomicAdd(&count[d], 1) : 0;
        }
    }
}

__device__ __forceinline__ unsigned long long ldv_u64(const unsigned long long* p) {
    unsigned long long v;
    asm volatile("ld.volatile.global.u64 %0, [%1];" : "=l"(v) : "l"(p));
    return v;
}

// Fused exclusive scan (decoupled lookback) + dinv + rowstart[n]=E. One launch.
__global__ void k_scan_lb(const int* __restrict__ count, int* __restrict__ rowstart,
                          float* __restrict__ dinv, unsigned long long* __restrict__ state,
                          int n, int E) {
    __shared__ int wsum[32], wpre[32];
    __shared__ int prefix_s;
    const int tid = threadIdx.x;
    const int lane = tid & 31, wid = tid >> 5;
    const int b = blockIdx.x;
    const int i = b * SCAN_B + tid;
    int v = (i < n) ? count[i] : 0;

    int x = v;
#pragma unroll
    for (int off = 1; off < 32; off <<= 1) {
        int t = __shfl_up_sync(0xffffffffu, x, off);
        if (lane >= off) x += t;
    }
    if (lane == 31) wsum[wid] = x;
    __syncthreads();

    if (wid == 0) {
        int s = wsum[lane];
        int y = s;
#pragma unroll
        for (int off = 1; off < 32; off <<= 1) {
            int t = __shfl_up_sync(0xffffffffu, y, off);
            if (lane >= off) y += t;
        }
        wpre[lane] = y - s;
        int total = __shfl_sync(0xffffffffu, y, 31);

        if (lane == 0)
            atomicExch(&state[b], (1ull << 32) | (unsigned)total);

        int prefix = 0;
        if (b > 0) {
            int base = b;
            while (true) {
                int p = base - 1 - lane;
                int fl = 2, val = 0;
                if (p >= 0) {
                    unsigned long long s64;
                    do { s64 = ldv_u64(&state[p]); fl = (int)(s64 >> 32); } while (fl == 0);
                    val = (int)(unsigned)s64;
                }
                unsigned m2 = __ballot_sync(0xffffffffu, fl == 2);
                if (m2) {
                    int firstLane = __ffs(m2) - 1;
                    prefix += __reduce_add_sync(0xffffffffu, (lane <= firstLane) ? val : 0);
                    break;
                } else {
                    prefix += __reduce_add_sync(0xffffffffu, val);
                    base -= 32;
                }
            }
        }
        if (lane == 0) {
            atomicExch(&state[b], (2ull << 32) | (unsigned)(prefix + total));
            prefix_s = prefix;
        }
    }
    __syncthreads();

    int incl = x + wpre[wid];
    if (i < n) {
        rowstart[i] = incl - v + prefix_s;
        dinv[i] = rsqrtf((float)v + 1.0f);
    }
    if (b == gridDim.x - 1 && tid == 0) rowstart[n] = E;
}

// 4 edges per thread, atomic-free via rank
__global__ void k_fill4(const int* __restrict__ src, const int* __restrict__ dst,
                        const int* __restrict__ rowstart, const int* __restrict__ rank,
                        int* __restrict__ srcs, int E, int n) {
    int i = blockIdx.x * blockDim.x + threadIdx.x;
    int e = i * 4;
    if (e + 3 < E) {
        int4 s4 = *((const int4*)(src + e));
        int4 d4 = *((const int4*)(dst + e));
        int4 r4 = *((const int4*)(rank + e));
        if ((unsigned)d4.x < (unsigned)n && (unsigned)s4.x < (unsigned)n) srcs[rowstart[d4.x] + r4.x] = s4.x;
        if ((unsigned)d4.y < (unsigned)n && (unsigned)s4.y < (unsigned)n) srcs[rowstart[d4.y] + r4.y] = s4.y;
        if ((unsigned)d4.z < (unsigned)n && (unsigned)s4.z < (unsigned)n) srcs[rowstart[d4.z] + r4.z] = s4.z;
        if ((unsigned)d4.w < (unsigned)n && (unsigned)s4.w < (unsigned)n) srcs[rowstart[d4.w] + r4.w] = s4.w;
    } else if (e < E) {
        for (; e < E; e++) {
            int d = dst[e], s = src[e];
            if ((unsigned)d < (unsigned)n && (unsigned)s < (unsigned)n)
                srcs[rowstart[d] + rank[e]] = s;
        }
    }
}

// ---------------- tf32 tensor-core GEMMs ----------------

__device__ __forceinline__ uint32_t f2tf32(float f) {
    uint32_t u;
    asm("cvt.rna.tf32.f32 %0, %1;" : "=r"(u) : "f"(f));
    return u;
}

// fp32 input, OUTC=128, WITH dinv scaling (msg1 = (x@W1)*dinv)
__global__ void k_gemm1_tc(const float* __restrict__ X, const float* __restrict__ W,
                           const float* __restrict__ dinv, __half* __restrict__ out, int N) {
    constexpr int OUTC = 128, BM = 128, BK = 32;
    constexpr int AP = 36, WP = OUTC + 4;
    constexpr int WARP_N = OUTC / 2, NNT = WARP_N / 8;
    __shared__ float As[BM * AP];
    __shared__ float Ws[BK * WP];

    const int tid  = threadIdx.x;
    const int warp = tid >> 5, lane = tid & 31;
    const int wm = warp >> 1, wn = warp & 1;
    const int g = lane >> 2, tig = lane & 3;
    const int rowBase = blockIdx.x * BM;

    float acc[2][NNT][4];
#pragma unroll
    for (int mt = 0; mt < 2; mt++)
#pragma unroll
        for (int nt = 0; nt < NNT; nt++)
#pragma unroll
            for (int c = 0; c < 4; c++) acc[mt][nt][c] = 0.f;

    for (int k0 = 0; k0 < 128; k0 += BK) {
#pragma unroll
        for (int j = 0; j < 4; j++) {
            int i4  = tid + j * 256;
            int row = i4 >> 3;
            int col = (i4 & 7) * 4;
            float4 v = make_float4(0.f, 0.f, 0.f, 0.f);
            if (rowBase + row < N)
                v = *((const float4*)(X + (size_t)(rowBase + row) * 128 + k0 + col));
            float* p = &As[row * AP + col];
            p[0] = __uint_as_float(f2tf32(v.x));
            p[1] = __uint_as_float(f2tf32(v.y));
            p[2] = __uint_as_float(f2tf32(v.z));
            p[3] = __uint_as_float(f2tf32(v.w));
        }
#pragma unroll
        for (int j = 0; j < 4; j++) {
            int i4  = tid + j * 256;
            int row = i4 >> 5;
            int col = (i4 & 31) * 4;
            float4 v = *((const float4*)(W + (size_t)(k0 + row) * OUTC + col));
            float* p = &Ws[row * WP + col];
            p[0] = __uint_as_float(f2tf32(v.x));
            p[1] = __uint_as_float(f2tf32(v.y));
            p[2] = __uint_as_float(f2tf32(v.z));
            p[3] = __uint_as_float(f2tf32(v.w));
        }
        __syncthreads();

#pragma unroll
        for (int kk = 0; kk < BK / 8; kk++) {
            int k = kk * 8;
            uint32_t a[2][4];
#pragma unroll
            for (int mt = 0; mt < 2; mt++) {
                int ar = wm * 32 + mt * 16;
                a[mt][0] = __float_as_uint(As[(ar + g)     * AP + k + tig]);
                a[mt][1] = __float_as_uint(As[(ar + g + 8) * AP + k + tig]);
                a[mt][2] = __float_as_uint(As[(ar + g)     * AP + k + tig + 4]);
                a[mt][3] = __float_as_uint(As[(ar + g + 8) * AP + k + tig + 4]);
            }
#pragma unroll
            for (int nt = 0; nt < NNT; nt++) {
                int nc = wn * WARP_N + nt * 8;
                uint32_t b0 = __float_as_uint(Ws[(k + tig)     * WP + nc + g]);
                uint32_t b1 = __float_as_uint(Ws[(k + tig + 4) * WP + nc + g]);
#pragma unroll
                for (int mt = 0; mt < 2; mt++) {
                    asm volatile(
                        "mma.sync.aligned.m16n8k8.row.col.f32.tf32.tf32.f32 "
                        "{%0,%1,%2,%3}, {%4,%5,%6,%7}, {%8,%9}, {%0,%1,%2,%3};"
                        : "+f"(acc[mt][nt][0]), "+f"(acc[mt][nt][1]),
                          "+f"(acc[mt][nt][2]), "+f"(acc[mt][nt][3])
                        : "r"(a[mt][0]), "r"(a[mt][1]), "r"(a[mt][2]), "r"(a[mt][3]),
                          "r"(b0), "r"(b1));
                }
            }
        }
        __syncthreads();
    }

#pragma unroll
    for (int mt = 0; mt < 2; mt++) {
        int r0 = rowBase + wm * 32 + mt * 16 + g;
        int r1 = r0 + 8;
        float dv0 = (r0 < N) ? dinv[r0] : 0.f;
        float dv1 = (r1 < N) ? dinv[r1] : 0.f;
#pragma unroll
        for (int nt = 0; nt < NNT; nt++) {
            int col = wn * WARP_N + nt * 8 + tig * 2;
            if (r0 < N)
                *((__half2*)(out + (size_t)r0 * OUTC + col)) =
                    __floats2half2_rn(acc[mt][nt][0] * dv0, acc[mt][nt][1] * dv0);
            if (r1 < N)
                *((__half2*)(out + (size_t)r1 * OUTC + col)) =
                    __floats2half2_rn(acc[mt][nt][2] * dv1, acc[mt][nt][3] * dv1);
        }
    }
}

// fp16 input, OUTC=64, dinv scaling (msg2 = (h1@W2)*dinv)
__global__ void k_gemm2_tc(const __half* __restrict__ Xh, const float* __restrict__ W,
                           const float* __restrict__ dinv, __half* __restrict__ out,
                           int Nrows) {
    constexpr int OUTC = 64, BM = 128, BK = 32;
    constexpr int AP = 36, WP = OUTC + 4;
    constexpr int WARP_N = OUTC / 2, NNT = WARP_N / 8;   // 32, 4
    __shared__ float As[BM * AP];
    __shared__ float Ws[BK * WP];

    const int tid  = threadIdx.x;
    const int warp = tid >> 5, lane = tid & 31;
    const int wm = warp >> 1, wn = warp & 1;
    const int g = lane >> 2, tig = lane & 3;
    const int rowBase = blockIdx.x * BM;

    float acc[2][NNT][4];
#pragma unroll
    for (int mt = 0; mt < 2; mt++)
#pragma unroll
        for (int nt = 0; nt < NNT; nt++)
#pragma unroll
            for (int c = 0; c < 4; c++) acc[mt][nt][c] = 0.f;

    for (int k0 = 0; k0 < 128; k0 += BK) {
#pragma unroll
        for (int j = 0; j < 2; j++) {
            int i4  = tid + j * 256;
            int row = i4 >> 2;
            int c8  = (i4 & 3) * 8;
            uint4 u = make_uint4(0, 0, 0, 0);
            if (rowBase + row < Nrows)
                u = *((const uint4*)(Xh + (size_t)(rowBase + row) * 128 + k0 + c8));
            const __half2* h2 = (const __half2*)&u;
            float* p = &As[row * AP + c8];
#pragma unroll
            for (int q = 0; q < 4; q++) {
                float2 f = __half22float2(h2[q]);
                p[q * 2 + 0] = __uint_as_float(f2tf32(f.x));
                p[q * 2 + 1] = __uint_as_float(f2tf32(f.y));
            }
        }
#pragma unroll
        for (int j = 0; j < 2; j++) {
            int i4  = tid + j * 256;
            int row = i4 >> 4;
            int col = (i4 & 15) * 4;
            float4 v = *((const float4*)(W + (size_t)(k0 + row) * OUTC + col));
            float* p = &Ws[row * WP + col];
            p[0] = __uint_as_float(f2tf32(v.x));
            p[1] = __uint_as_float(f2tf32(v.y));
            p[2] = __uint_as_float(f2tf32(v.z));
            p[3] = __uint_as_float(f2tf32(v.w));
        }
        __syncthreads();

#pragma unroll
        for (int kk = 0; kk < BK / 8; kk++) {
            int k = kk * 8;
            uint32_t a[2][4];
#pragma unroll
            for (int mt = 0; mt < 2; mt++) {
                int ar = wm * 32 + mt * 16;
                a[mt][0] = __float_as_uint(As[(ar + g)     * AP + k + tig]);
                a[mt][1] = __float_as_uint(As[(ar + g + 8) * AP + k + tig]);
                a[mt][2] = __float_as_uint(As[(ar + g)     * AP + k + tig + 4]);
                a[mt][3] = __float_as_uint(As[(ar + g + 8) * AP + k + tig + 4]);
            }
#pragma unroll
            for (int nt = 0; nt < NNT; nt++) {
                int nc = wn * WARP_N + nt * 8;
                uint32_t b0 = __float_as_uint(Ws[(k + tig)     * WP + nc + g]);
                uint32_t b1 = __float_as_uint(Ws[(k + tig + 4) * WP + nc + g]);
#pragma unroll
                for (int mt = 0; mt < 2; mt++) {
                    asm volatile(
                        "mma.sync.aligned.m16n8k8.row.col.f32.tf32.tf32.f32 "
                        "{%0,%1,%2,%3}, {%4,%5,%6,%7}, {%8,%9}, {%0,%1,%2,%3};"
                        : "+f"(acc[mt][nt][0]), "+f"(acc[mt][nt][1]),
                          "+f"(acc[mt][nt][2]), "+f"(acc[mt][nt][3])
                        : "r"(a[mt][0]), "r"(a[mt][1]), "r"(a[mt][2]), "r"(a[mt][3]),
                          "r"(b0), "r"(b1));
                }
            }
        }
        __syncthreads();
    }

#pragma unroll
    for (int mt = 0; mt < 2; mt++) {
        int r0 = rowBase + wm * 32 + mt * 16 + g;
        int r1 = r0 + 8;
        float dv0 = (r0 < Nrows) ? dinv[r0] : 0.f;
        float dv1 = (r1 < Nrows) ? dinv[r1] : 0.f;
#pragma unroll
        for (int nt = 0; nt < NNT; nt++) {
            int col = wn * WARP_N + nt * 8 + tig * 2;
            if (r0 < Nrows)
                *((__half2*)(out + (size_t)r0 * OUTC + col)) =
                    __floats2half2_rn(acc[mt][nt][0] * dv0, acc[mt][nt][1] * dv0);
            if (r1 < Nrows)
                *((__half2*)(out + (size_t)r1 * OUTC + col)) =
                    __floats2half2_rn(acc[mt][nt][2] * dv1, acc[mt][nt][3] * dv1);
        }
    }
}

// ---------------- gathers ----------------
// Layer 1: msg pre-scaled by dinv[src]. h1h = half(relu((Σ msg[s] + msg[n])·dinv[n] + b1))

__global__ void k_gather128h(const __half* __restrict__ g, const int* __restrict__ rowstart,
                             const int* __restrict__ srcs, const float* __restrict__ dinv,
                             const float* __restrict__ bias, __half* __restrict__ out, int n) {
    int node = (blockIdx.x * blockDim.x + threadIdx.x) >> 5;
    int lane = threadIdx.x & 31;
    if (node >= n) return;
    int e0 = rowstart[node], e1 = rowstart[node + 1];
    float dvn = dinv[node];

    float acc0, acc1, acc2, acc3;
    {
        uint2 u = *((const uint2*)(g + (size_t)node * 128 + lane * 4));
        float2 a = __half22float2(*(const __half2*)&u.x);
        float2 b = __half22float2(*(const __half2*)&u.y);
        acc0 = a.x; acc1 = a.y; acc2 = b.x; acc3 = b.y;
    }
    int e = e0;
    while (e1 - e >= 32) {
        int idx = srcs[e + lane];
#pragma unroll
        for (int k = 0; k < 32; k++) {
            int s = __shfl_sync(0xffffffffu, idx, k);
            uint2 u = *((const uint2*)(g + (size_t)s * 128 + lane * 4));
            float2 a = __half22float2(*(const __half2*)&u.x);
            float2 b = __half22float2(*(const __half2*)&u.y);
            acc0 += a.x; acc1 += a.y; acc2 += b.x; acc3 += b.y;
        }
        e += 32;
    }
    if (e < e1) {
        int m = e1 - e;
        int idx = (lane < m) ? srcs[e + lane] : 0;
#pragma unroll 8
        for (int k = 0; k < m; k++) {
            int s = __shfl_sync(0xffffffffu, idx, k);
            uint2 u = *((const uint2*)(g + (size_t)s * 128 + lane * 4));
            float2 a = __half22float2(*(const __half2*)&u.x);
            float2 b = __half22float2(*(const __half2*)&u.y);
            acc0 += a.x; acc1 += a.y; acc2 += b.x; acc3 += b.y;
        }
    }
    float4 bv = ((const float4*)bias)[lane];
    __half2 h01 = __floats2half2_rn(fmaxf(acc0 * dvn + bv.x, 0.f),
                                    fmaxf(acc1 * dvn + bv.y, 0.f));
    __half2 h23 = __floats2half2_rn(fmaxf(acc2 * dvn + bv.z, 0.f),
                                    fmaxf(acc3 * dvn + bv.w, 0.f));
    uint2 st;
    st.x = *(const uint32_t*)&h01;
    st.y = *(const uint32_t*)&h23;
    *((uint2*)(out + (size_t)node * 128 + lane * 4)) = st;
}

// Layer 2: out = (Σ msg2[s] + msg2[n])·dinv[n] + b2   (msg2 pre-scaled)
__global__ void k_gather64h(const __half* __restrict__ g, const int* __restrict__ rowstart,
                            const int* __restrict__ srcs, const float* __restrict__ dinv,
                            const float* __restrict__ bias, float* __restrict__ out, int n) {
    int node = (blockIdx.x * blockDim.x + threadIdx.x) >> 5;
    int lane = threadIdx.x & 31;
    if (node >= n) return;
    int e0 = rowstart[node], e1 = rowstart[node + 1];

    float2 acc = __half22float2(*((const __half2*)(g + (size_t)node * 64 + lane * 2)));
    int e = e0;
    while (e1 - e >= 32) {
        int idx = srcs[e + lane];
#pragma unroll
        for (int k = 0; k < 32; k++) {
            int s = __shfl_sync(0xffffffffu, idx, k);
            float2 v = __half22float2(*((const __half2*)(g + (size_t)s * 64 + lane * 2)));
            acc.x += v.x; acc.y += v.y;
        }
        e += 32;
    }
    if (e < e1) {
        int m = e1 - e;
        int idx = (lane < m) ? srcs[e + lane] : 0;
#pragma unroll 8
        for (int k = 0; k < m; k++) {
            int s = __shfl_sync(0xffffffffu, idx, k);
            float2 v = __half22float2(*((const __half2*)(g + (size_t)s * 64 + lane * 2)));
            acc.x += v.x; acc.y += v.y;
        }
    }
    float dv = dinv[node];
    float2 bv = ((const float2*)bias)[lane];
    float2 r;
    r.x = acc.x * dv + bv.x;
    r.y = acc.y * dv + bv.y;
    ((float2*)(out + (size_t)node * 64))[lane] = r;
}

// ---------------- launch ----------------

extern "C" void kernel_launch(void* const* d_in, const int* in_sizes, int n_in,
                              void* d_out, int out_size) {
    const float* x   = (const float*)d_in[0];
    const int*   ei  = (const int*)d_in[1];    // int32 (JAX x64 disabled)
    const float* W1  = (const float*)d_in[2];
    const float* b1  = (const float*)d_in[3];
    const float* W2  = (const float*)d_in[4];
    const float* b2  = (const float*)d_in[5];
    float*       out = (float*)d_out;

    const int N = in_sizes[0] / 128;
    const int E = in_sizes[1] / 2;
    const int* srcp = ei;
    const int* dstp = ei + E;

    float*  dinv;  cudaGetSymbolAddress((void**)&dinv,  g_dinv);
    int*    count; cudaGetSymbolAddress((void**)&count, g_count);
    int*    rowst; cudaGetSymbolAddress((void**)&rowst, g_rowstart);
    int*    rank;  cudaGetSymbolAddress((void**)&rank,  g_rank);
    unsigned long long* lbst; cudaGetSymbolAddress((void**)&lbst, g_lbstate);
    int*    srcs;  cudaGetSymbolAddress((void**)&srcs,  g_srcs);
    __half* msg;   cudaGetSymbolAddress((void**)&msg,   g_msg);
    __half* h1h;   cudaGetSymbolAddress((void**)&h1h,   g_h1h);
    __half* msg2;  cudaGetSymbolAddress((void**)&msg2,  g_msg2);

    static cudaStream_t s2 = nullptr;
    static cudaEvent_t evD = nullptr, evG1 = nullptr;
    if (!s2) {
        cudaStreamCreateWithFlags(&s2, cudaStreamNonBlocking);
        cudaEventCreateWithFlags(&evD, cudaEventDisableTiming);
        cudaEventCreateWithFlags(&evG1, cudaEventDisableTiming);
    }

    const int T = 256;
    const int nb = (N + SCAN_B - 1) / SCAN_B;   // 49

    // CSR prefix chain (stream 0): zero -> hist -> scan (produces dinv)
    k_zero2<<<(N + T - 1) / T, T>>>(count, N, (int*)lbst, NB_MAX * 2);
    k_hist4<<<(E / 4 + T) / T, T>>>(dstp, count, rank, E, N);
    k_scan_lb<<<nb, SCAN_B>>>(count, rowst, dinv, lbst, N, E);
    cudaEventRecord(evD, 0);

    // fork: GEMM1 (needs dinv) runs on s2 concurrently with fill on stream 0
    cudaStreamWaitEvent(s2, evD, 0);
    k_gemm1_tc<<<(N + 127) / 128, 256, 0, s2>>>(x, W1, dinv, msg, N);
    cudaEventRecord(evG1, s2);

    k_fill4<<<(E / 4 + T) / T, T>>>(srcp, dstp, rowst, rank, srcs, E, N);

    // join: gather1 needs fill (stream 0) + GEMM1 (s2)
    cudaStreamWaitEvent(0, evG1, 0);
    k_gather128h<<<(N * 32 + T - 1) / T, T>>>(msg, rowst, srcs, dinv, b1, h1h, N);

    // layer 2
    k_gemm2_tc<<<(N + 127) / 128, 256>>>(h1h, W2, dinv, msg2, N);
    k_gather64h<<<(N * 32 + T - 1) / T, T>>>(msg2, rowst, srcs, dinv, b2, out, N);
}

// round 14
// speedup vs baseline: 1.1698x; 1.0738x over previous
#include <cuda_runtime.h>
#include <cuda_fp16.h>
#include <cstdint>

// N=50000, E=1600000, F=128, H=128, C=64
#define NMAX 50000
#define EMAX 1600000
#define SCAN_B 1024
#define NB_MAX 64

// Scratch (no dynamic allocation allowed)
__device__ __align__(16) float  g_dinv[NMAX];
__device__ __align__(16) int    g_count[NMAX];
__device__ __align__(16) int    g_rowstart[NMAX + 1];
__device__ __align__(16) int    g_rank[EMAX];
__device__ __align__(16) unsigned long long g_lbstate[NB_MAX];
__device__ __align__(16) int    g_srcs[EMAX];
__device__ __align__(16) __half g_msg [(size_t)NMAX * 128];  // msg1 = (x@W1)*dinv
__device__ __align__(16) __half g_h1h [(size_t)NMAX * 128];  // h1 post-relu (fp16)
__device__ __align__(16) __half g_msg2[(size_t)NMAX * 64];   // msg2 = (h1@W2)*dinv

// ---------------- CSR build ----------------

__global__ void k_zero2(int* a, int na, int* b, int nb) {
    int i = blockIdx.x * blockDim.x + threadIdx.x;
    if (i < na) a[i] = 0;
    if (i < nb) b[i] = 0;
}

__global__ void k_hist4(const int* __restrict__ dst, int* __restrict__ count,
                        int* __restrict__ rank, int E, int n) {
    int i = blockIdx.x * blockDim.x + threadIdx.x;
    int e = i * 4;
    if (e + 3 < E) {
        int4 d = *((const int4*)(dst + e));
        int4 r;
        r.x = ((unsigned)d.x < (unsigned)n) ? atomicAdd(&count[d.x], 1) : 0;
        r.y = ((unsigned)d.y < (unsigned)n) ? atomicAdd(&count[d.y], 1) : 0;
        r.z = ((unsigned)d.z < (unsigned)n) ? atomicAdd(&count[d.z], 1) : 0;
        r.w = ((unsigned)d.w < (unsigned)n) ? atomicAdd(&count[d.w], 1) : 0;
        *((int4*)(rank + e)) = r;
    } else if (e < E) {
        for (; e < E; e++) {
            int d = dst[e];
            rank[e] = ((unsigned)d < (unsigned)n) ? atomicAdd(&count[d], 1) : 0;
        }
    }
}

__device__ __forceinline__ unsigned long long ldv_u64(const unsigned long long* p) {
    unsigned long long v;
    asm volatile("ld.volatile.global.u64 %0, [%1];" : "=l"(v) : "l"(p));
    return v;
}

__global__ void k_scan_lb(const int* __restrict__ count, int* __restrict__ rowstart,
                          float* __restrict__ dinv, unsigned long long* __restrict__ state,
                          int n, int E) {
    __shared__ int wsum[32], wpre[32];
    __shared__ int prefix_s;
    const int tid = threadIdx.x;
    const int lane = tid & 31, wid = tid >> 5;
    const int b = blockIdx.x;
    const int i = b * SCAN_B + tid;
    int v = (i < n) ? count[i] : 0;

    int x = v;
#pragma unroll
    for (int off = 1; off < 32; off <<= 1) {
        int t = __shfl_up_sync(0xffffffffu, x, off);
        if (lane >= off) x += t;
    }
    if (lane == 31) wsum[wid] = x;
    __syncthreads();

    if (wid == 0) {
        int s = wsum[lane];
        int y = s;
#pragma unroll
        for (int off = 1; off < 32; off <<= 1) {
            int t = __shfl_up_sync(0xffffffffu, y, off);
            if (lane >= off) y += t;
        }
        wpre[lane] = y - s;
        int total = __shfl_sync(0xffffffffu, y, 31);

        if (lane == 0)
            atomicExch(&state[b], (1ull << 32) | (unsigned)total);

        int prefix = 0;
        if (b > 0) {
            int base = b;
            while (true) {
                int p = base - 1 - lane;
                int fl = 2, val = 0;
                if (p >= 0) {
                    unsigned long long s64;
                    do { s64 = ldv_u64(&state[p]); fl = (int)(s64 >> 32); } while (fl == 0);
                    val = (int)(unsigned)s64;
                }
                unsigned m2 = __ballot_sync(0xffffffffu, fl == 2);
                if (m2) {
                    int firstLane = __ffs(m2) - 1;
                    prefix += __reduce_add_sync(0xffffffffu, (lane <= firstLane) ? val : 0);
                    break;
                } else {
                    prefix += __reduce_add_sync(0xffffffffu, val);
                    base -= 32;
                }
            }
        }
        if (lane == 0) {
            atomicExch(&state[b], (2ull << 32) | (unsigned)(prefix + total));
            prefix_s = prefix;
        }
    }
    __syncthreads();

    int incl = x + wpre[wid];
    if (i < n) {
        rowstart[i] = incl - v + prefix_s;
        dinv[i] = rsqrtf((float)v + 1.0f);
    }
    if (b == gridDim.x - 1 && tid == 0) rowstart[n] = E;
}

__global__ void k_fill4(const int* __restrict__ src, const int* __restrict__ dst,
                        const int* __restrict__ rowstart, const int* __restrict__ rank,
                        int* __restrict__ srcs, int E, int n) {
    int i = blockIdx.x * blockDim.x + threadIdx.x;
    int e = i * 4;
    if (e + 3 < E) {
        int4 s4 = *((const int4*)(src + e));
        int4 d4 = *((const int4*)(dst + e));
        int4 r4 = *((const int4*)(rank + e));
        if ((unsigned)d4.x < (unsigned)n && (unsigned)s4.x < (unsigned)n) srcs[rowstart[d4.x] + r4.x] = s4.x;
        if ((unsigned)d4.y < (unsigned)n && (unsigned)s4.y < (unsigned)n) srcs[rowstart[d4.y] + r4.y] = s4.y;
        if ((unsigned)d4.z < (unsigned)n && (unsigned)s4.z < (unsigned)n) srcs[rowstart[d4.z] + r4.z] = s4.z;
        if ((unsigned)d4.w < (unsigned)n && (unsigned)s4.w < (unsigned)n) srcs[rowstart[d4.w] + r4.w] = s4.w;
    } else if (e < E) {
        for (; e < E; e++) {
            int d = dst[e], s = src[e];
            if ((unsigned)d < (unsigned)n && (unsigned)s < (unsigned)n)
                srcs[rowstart[d] + rank[e]] = s;
        }
    }
}

// ---------------- fp16 tensor-core GEMMs (mma.m16n8k16, fp32 accum) ----------------
// Smem layouts (uint32 = half2 units):
//   Ap[row][k2]  row stride AP2=20  (k2 = k/2, 16 half2 per 32-k row + pad)
//   Wsp[k2][col] row stride OUTCP   (col in halves? no: col index, one half2 per (k2,col)
//                holds W[2*k2][col], W[2*k2+1][col])

#define MMA_F16(d, a, b)                                                        \
    asm volatile(                                                               \
        "mma.sync.aligned.m16n8k16.row.col.f32.f16.f16.f32 "                    \
        "{%0,%1,%2,%3}, {%4,%5,%6,%7}, {%8,%9}, {%0,%1,%2,%3};"                 \
        : "+f"((d)[0]), "+f"((d)[1]), "+f"((d)[2]), "+f"((d)[3])                \
        : "r"((a)[0]), "r"((a)[1]), "r"((a)[2]), "r"((a)[3]),                   \
          "r"((b)[0]), "r"((b)[1]))

// GEMM1: fp32 X, OUTC=128, dinv computed INLINE from count (depends on hist only).
__global__ void k_gemm1_tc(const float* __restrict__ X, const float* __restrict__ W,
                           const int* __restrict__ count, __half* __restrict__ out, int N) {
    constexpr int OUTC = 128, BM = 128;
    constexpr int AP2 = 20, OUTCP = OUTC + 4;
    constexpr int WARP_N = 64, NNT = WARP_N / 8;   // 8
    __shared__ uint32_t Ap[BM * AP2];              // 10240 B
    __shared__ uint32_t Wsp[16 * OUTCP];           // 8448 B

    const int tid  = threadIdx.x;
    const int warp = tid >> 5, lane = tid & 31;
    const int wm = warp >> 1, wn = warp & 1;
    const int g = lane >> 2, tig = lane & 3;
    const int rowBase = blockIdx.x * BM;

    float acc[2][NNT][4];
#pragma unroll
    for (int mt = 0; mt < 2; mt++)
#pragma unroll
        for (int nt = 0; nt < NNT; nt++)
#pragma unroll
            for (int c = 0; c < 4; c++) acc[mt][nt][c] = 0.f;

    for (int k0 = 0; k0 < 128; k0 += 32) {
        // A tile: 128 rows x 32 k = 1024 float4 reads -> half2 pairs
#pragma unroll
        for (int j = 0; j < 4; j++) {
            int i4  = tid + j * 256;
            int row = i4 >> 3;
            int c4  = i4 & 7;                      // which float4 in the 32-k row
            float4 v = make_float4(0.f, 0.f, 0.f, 0.f);
            if (rowBase + row < N)
                v = *((const float4*)(X + (size_t)(rowBase + row) * 128 + k0 + c4 * 4));
            __half2 h0 = __floats2half2_rn(v.x, v.y);
            __half2 h1 = __floats2half2_rn(v.z, v.w);
            uint2 st;
            st.x = *(const uint32_t*)&h0;
            st.y = *(const uint32_t*)&h1;
            *((uint2*)&Ap[row * AP2 + c4 * 2]) = st;
        }
        // W tile: 32 k x 128 cols; pair k rows -> Wsp[k2][c]
#pragma unroll
        for (int j = 0; j < 2; j++) {
            int i  = tid + j * 256;                // 0..511
            int k2 = i >> 5;                       // 0..15
            int c  = (i & 31) * 4;
            float4 v0 = *((const float4*)(W + (size_t)(k0 + 2 * k2)     * OUTC + c));
            float4 v1 = *((const float4*)(W + (size_t)(k0 + 2 * k2 + 1) * OUTC + c));
            __half2 h0 = __floats2half2_rn(v0.x, v1.x);
            __half2 h1 = __floats2half2_rn(v0.y, v1.y);
            __half2 h2 = __floats2half2_rn(v0.z, v1.z);
            __half2 h3 = __floats2half2_rn(v0.w, v1.w);
            uint4 st;
            st.x = *(const uint32_t*)&h0; st.y = *(const uint32_t*)&h1;
            st.z = *(const uint32_t*)&h2; st.w = *(const uint32_t*)&h3;
            *((uint4*)&Wsp[k2 * OUTCP + c]) = st;
        }
        __syncthreads();

#pragma unroll
        for (int kk = 0; kk < 2; kk++) {           // two 16-k slices
            int k2b = kk * 8;
            uint32_t a[2][4];
#pragma unroll
            for (int mt = 0; mt < 2; mt++) {
                int ar = wm * 32 + mt * 16;
                a[mt][0] = Ap[(ar + g)     * AP2 + k2b + tig];
                a[mt][1] = Ap[(ar + g + 8) * AP2 + k2b + tig];
                a[mt][2] = Ap[(ar + g)     * AP2 + k2b + 4 + tig];
                a[mt][3] = Ap[(ar + g + 8) * AP2 + k2b + 4 + tig];
            }
#pragma unroll
            for (int nt = 0; nt < NNT; nt++) {
                int nc = wn * WARP_N + nt * 8;
                uint32_t b[2];
                b[0] = Wsp[(k2b + tig)     * OUTCP + nc + g];
                b[1] = Wsp[(k2b + 4 + tig) * OUTCP + nc + g];
#pragma unroll
                for (int mt = 0; mt < 2; mt++) MMA_F16(acc[mt][nt], a[mt], b);
            }
        }
        __syncthreads();
    }

#pragma unroll
    for (int mt = 0; mt < 2; mt++) {
        int r0 = rowBase + wm * 32 + mt * 16 + g;
        int r1 = r0 + 8;
        float dv0 = (r0 < N) ? rsqrtf((float)count[r0] + 1.0f) : 0.f;
        float dv1 = (r1 < N) ? rsqrtf((float)count[r1] + 1.0f) : 0.f;
#pragma unroll
        for (int nt = 0; nt < NNT; nt++) {
            int col = wn * WARP_N + nt * 8 + tig * 2;
            if (r0 < N)
                *((__half2*)(out + (size_t)r0 * OUTC + col)) =
                    __floats2half2_rn(acc[mt][nt][0] * dv0, acc[mt][nt][1] * dv0);
            if (r1 < N)
                *((__half2*)(out + (size_t)r1 * OUTC + col)) =
                    __floats2half2_rn(acc[mt][nt][2] * dv1, acc[mt][nt][3] * dv1);
        }
    }
}

// GEMM2: fp16 input, OUTC=64, dinv from array (ready long before).
__global__ void k_gemm2_tc(const __half* __restrict__ Xh, const float* __restrict__ W,
                           const float* __restrict__ dinv, __half* __restrict__ out,
                           int Nrows) {
    constexpr int OUTC = 64, BM = 128;
    constexpr int AP2 = 20, OUTCP = OUTC + 4;
    constexpr int WARP_N = 32, NNT = WARP_N / 8;   // 4
    __shared__ uint32_t Ap[BM * AP2];
    __shared__ uint32_t Wsp[16 * OUTCP];

    const int tid  = threadIdx.x;
    const int warp = tid >> 5, lane = tid & 31;
    const int wm = warp >> 1, wn = warp & 1;
    const int g = lane >> 2, tig = lane & 3;
    const int rowBase = blockIdx.x * BM;

    float acc[2][NNT][4];
#pragma unroll
    for (int mt = 0; mt < 2; mt++)
#pragma unroll
        for (int nt = 0; nt < NNT; nt++)
#pragma unroll
            for (int c = 0; c < 4; c++) acc[mt][nt][c] = 0.f;

    for (int k0 = 0; k0 < 128; k0 += 32) {
        // A tile: fp16 direct copy; 128 rows x 32 halves = 512 uint4, 2/thread
#pragma unroll
        for (int j = 0; j < 2; j++) {
            int i4  = tid + j * 256;
            int row = i4 >> 2;
            int q   = i4 & 3;                      // which uint4 (8 halves)
            uint4 u = make_uint4(0, 0, 0, 0);
            if (rowBase + row < Nrows)
                u = *((const uint4*)(Xh + (size_t)(rowBase + row) * 128 + k0 + q * 8));
            *((uint4*)&Ap[row * AP2 + q * 4]) = u;
        }
        // W tile: 32 k x 64 cols; 16 k2 x 16 float4-pairs = 256 tasks, 1/thread
        {
            int i  = tid;
            int k2 = i >> 4;                       // 0..15
            int c  = (i & 15) * 4;
            float4 v0 = *((const float4*)(W + (size_t)(k0 + 2 * k2)     * OUTC + c));
            float4 v1 = *((const float4*)(W + (size_t)(k0 + 2 * k2 + 1) * OUTC + c));
            __half2 h0 = __floats2half2_rn(v0.x, v1.x);
            __half2 h1 = __floats2half2_rn(v0.y, v1.y);
            __half2 h2 = __floats2half2_rn(v0.z, v1.z);
            __half2 h3 = __floats2half2_rn(v0.w, v1.w);
            uint4 st;
            st.x = *(const uint32_t*)&h0; st.y = *(const uint32_t*)&h1;
            st.z = *(const uint32_t*)&h2; st.w = *(const uint32_t*)&h3;
            *((uint4*)&Wsp[k2 * OUTCP + c]) = st;
        }
        __syncthreads();

#pragma unroll
        for (int kk = 0; kk < 2; kk++) {
            int k2b = kk * 8;
            uint32_t a[2][4];
#pragma unroll
            for (int mt = 0; mt < 2; mt++) {
                int ar = wm * 32 + mt * 16;
                a[mt][0] = Ap[(ar + g)     * AP2 + k2b + tig];
                a[mt][1] = Ap[(ar + g + 8) * AP2 + k2b + tig];
                a[mt][2] = Ap[(ar + g)     * AP2 + k2b + 4 + tig];
                a[mt][3] = Ap[(ar + g + 8) * AP2 + k2b + 4 + tig];
            }
#pragma unroll
            for (int nt = 0; nt < NNT; nt++) {
                int nc = wn * WARP_N + nt * 8;
                uint32_t b[2];
                b[0] = Wsp[(k2b + tig)     * OUTCP + nc + g];
                b[1] = Wsp[(k2b + 4 + tig) * OUTCP + nc + g];
#pragma unroll
                for (int mt = 0; mt < 2; mt++) MMA_F16(acc[mt][nt], a[mt], b);
            }
        }
        __syncthreads();
    }

#pragma unroll
    for (int mt = 0; mt < 2; mt++) {
        int r0 = rowBase + wm * 32 + mt * 16 + g;
        int r1 = r0 + 8;
        float dv0 = (r0 < Nrows) ? dinv[r0] : 0.f;
        float dv1 = (r1 < Nrows) ? dinv[r1] : 0.f;
#pragma unroll
        for (int nt = 0; nt < NNT; nt++) {
            int col = wn * WARP_N + nt * 8 + tig * 2;
            if (r0 < Nrows)
                *((__half2*)(out + (size_t)r0 * OUTC + col)) =
                    __floats2half2_rn(acc[mt][nt][0] * dv0, acc[mt][nt][1] * dv0);
            if (r1 < Nrows)
                *((__half2*)(out + (size_t)r1 * OUTC + col)) =
                    __floats2half2_rn(acc[mt][nt][2] * dv1, acc[mt][nt][3] * dv1);
        }
    }
}

// ---------------- gathers ----------------
// Layer 1: msg pre-scaled by dinv[src]. h1h = half(relu((Σ msg[s] + msg[n])·dinv[n] + b1))

__global__ void k_gather128h(const __half* __restrict__ g, const int* __restrict__ rowstart,
                             const int* __restrict__ srcs, const float* __restrict__ dinv,
                             const float* __restrict__ bias, __half* __restrict__ out, int n) {
    int node = (blockIdx.x * blockDim.x + threadIdx.x) >> 5;
    int lane = threadIdx.x & 31;
    if (node >= n) return;
    int e0 = rowstart[node], e1 = rowstart[node + 1];
    float dvn = dinv[node];

    float acc0, acc1, acc2, acc3;
    {
        uint2 u = *((const uint2*)(g + (size_t)node * 128 + lane * 4));
        float2 a = __half22float2(*(const __half2*)&u.x);
        float2 b = __half22float2(*(const __half2*)&u.y);
        acc0 = a.x; acc1 = a.y; acc2 = b.x; acc3 = b.y;
    }
    int e = e0;
    while (e1 - e >= 32) {
        int idx = srcs[e + lane];
#pragma unroll
        for (int k = 0; k < 32; k++) {
            int s = __shfl_sync(0xffffffffu, idx, k);
            uint2 u = *((const uint2*)(g + (size_t)s * 128 + lane * 4));
            float2 a = __half22float2(*(const __half2*)&u.x);
            float2 b = __half22float2(*(const __half2*)&u.y);
            acc0 += a.x; acc1 += a.y; acc2 += b.x; acc3 += b.y;
        }
        e += 32;
    }
    if (e < e1) {
        int m = e1 - e;
        int idx = (lane < m) ? srcs[e + lane] : 0;
#pragma unroll 8
        for (int k = 0; k < m; k++) {
            int s = __shfl_sync(0xffffffffu, idx, k);
            uint2 u = *((const uint2*)(g + (size_t)s * 128 + lane * 4));
            float2 a = __half22float2(*(const __half2*)&u.x);
            float2 b = __half22float2(*(const __half2*)&u.y);
            acc0 += a.x; acc1 += a.y; acc2 += b.x; acc3 += b.y;
        }
    }
    float4 bv = ((const float4*)bias)[lane];
    __half2 h01 = __floats2half2_rn(fmaxf(acc0 * dvn + bv.x, 0.f),
                                    fmaxf(acc1 * dvn + bv.y, 0.f));
    __half2 h23 = __floats2half2_rn(fmaxf(acc2 * dvn + bv.z, 0.f),
                                    fmaxf(acc3 * dvn + bv.w, 0.f));
    uint2 st;
    st.x = *(const uint32_t*)&h01;
    st.y = *(const uint32_t*)&h23;
    *((uint2*)(out + (size_t)node * 128 + lane * 4)) = st;
}

// Layer 2: out = (Σ msg2[s] + msg2[n])·dinv[n] + b2
__global__ void k_gather64h(const __half* __restrict__ g, const int* __restrict__ rowstart,
                            const int* __restrict__ srcs, const float* __restrict__ dinv,
                            const float* __restrict__ bias, float* __restrict__ out, int n) {
    int node = (blockIdx.x * blockDim.x + threadIdx.x) >> 5;
    int lane = threadIdx.x & 31;
    if (node >= n) return;
    int e0 = rowstart[node], e1 = rowstart[node + 1];

    float2 acc = __half22float2(*((const __half2*)(g + (size_t)node * 64 + lane * 2)));
    int e = e0;
    while (e1 - e >= 32) {
        int idx = srcs[e + lane];
#pragma unroll
        for (int k = 0; k < 32; k++) {
            int s = __shfl_sync(0xffffffffu, idx, k);
            float2 v = __half22float2(*((const __half2*)(g + (size_t)s * 64 + lane * 2)));
            acc.x += v.x; acc.y += v.y;
        }
        e += 32;
    }
    if (e < e1) {
        int m = e1 - e;
        int idx = (lane < m) ? srcs[e + lane] : 0;
#pragma unroll 8
        for (int k = 0; k < m; k++) {
            int s = __shfl_sync(0xffffffffu, idx, k);
            float2 v = __half22float2(*((const __half2*)(g + (size_t)s * 64 + lane * 2)));
            acc.x += v.x; acc.y += v.y;
        }
    }
    float dv = dinv[node];
    float2 bv = ((const float2*)bias)[lane];
    float2 r;
    r.x = acc.x * dv + bv.x;
    r.y = acc.y * dv + bv.y;
    ((float2*)(out + (size_t)node * 64))[lane] = r;
}

// ---------------- launch ----------------

extern "C" void kernel_launch(void* const* d_in, const int* in_sizes, int n_in,
                              void* d_out, int out_size) {
    const float* x   = (const float*)d_in[0];
    const int*   ei  = (const int*)d_in[1];    // int32 (JAX x64 disabled)
    const float* W1  = (const float*)d_in[2];
    const float* b1  = (const float*)d_in[3];
    const float* W2  = (const float*)d_in[4];
    const float* b2  = (const float*)d_in[5];
    float*       out = (float*)d_out;

    const int N = in_sizes[0] / 128;
    const int E = in_sizes[1] / 2;
    const int* srcp = ei;
    const int* dstp = ei + E;

    float*  dinv;  cudaGetSymbolAddress((void**)&dinv,  g_dinv);
    int*    count; cudaGetSymbolAddress((void**)&count, g_count);
    int*    rowst; cudaGetSymbolAddress((void**)&rowst, g_rowstart);
    int*    rank;  cudaGetSymbolAddress((void**)&rank,  g_rank);
    unsigned long long* lbst; cudaGetSymbolAddress((void**)&lbst, g_lbstate);
    int*    srcs;  cudaGetSymbolAddress((void**)&srcs,  g_srcs);
    __half* msg;   cudaGetSymbolAddress((void**)&msg,   g_msg);
    __half* h1h;   cudaGetSymbolAddress((void**)&h1h,   g_h1h);
    __half* msg2;  cudaGetSymbolAddress((void**)&msg2,  g_msg2);

    static cudaStream_t s2 = nullptr;
    static cudaEvent_t evH = nullptr, evG1 = nullptr;
    if (!s2) {
        cudaStreamCreateWithFlags(&s2, cudaStreamNonBlocking);
        cudaEventCreateWithFlags(&evH, cudaEventDisableTiming);
        cudaEventCreateWithFlags(&evG1, cudaEventDisableTiming);
    }

    const int T = 256;
    const int nb = (N + SCAN_B - 1) / SCAN_B;   // 49

    // stream 0: zero -> hist
    k_zero2<<<(N + T - 1) / T, T>>>(count, N, (int*)lbst, NB_MAX * 2);
    k_hist4<<<(E / 4 + T) / T, T>>>(dstp, count, rank, E, N);
    cudaEventRecord(evH, 0);

    // fork: GEMM1 (needs only count — dinv computed inline) overlaps scan+fill
    cudaStreamWaitEvent(s2, evH, 0);
    k_gemm1_tc<<<(N + 127) / 128, 256, 0, s2>>>(x, W1, count, msg, N);
    cudaEventRecord(evG1, s2);

    // stream 0: scan -> fill
    k_scan_lb<<<nb, SCAN_B>>>(count, rowst, dinv, lbst, N, E);
    k_fill4<<<(E / 4 + T) / T, T>>>(srcp, dstp, rowst, rank, srcs, E, N);

    // join: gather1 needs fill + scan (stream 0) + GEMM1 (s2)
    cudaStreamWaitEvent(0, evG1, 0);
    k_gather128h<<<(N * 32 + T - 1) / T, T>>>(msg, rowst, srcs, dinv, b1, h1h, N);

    // layer 2
    k_gemm2_tc<<<(N + 127) / 128, 256>>>(h1h, W2, dinv, msg2, N);
    k_gather64h<<<(N * 32 + T - 1) / T, T>>>(msg2, rowst, srcs, dinv, b2, out, N);
}

// round 15
// speedup vs baseline: 1.1830x; 1.0113x over previous
#include <cuda_runtime.h>
#include <cuda_fp16.h>
#include <cstdint>

// N=50000, E=1600000, F=128, H=128, C=64
#define NMAX 50000
#define EMAX 1600000
#define SCAN_B 1024
#define NB_MAX 64

// Scratch (no dynamic allocation allowed).
// g_count / g_lbstate are zero at kernel_launch entry: statically zero-initialized
// at module load, and re-zeroed by k_gather128h's epilogue at the end of every call.
__device__ __align__(16) float  g_dinv[NMAX];
__device__ __align__(16) int    g_count[NMAX];
__device__ __align__(16) int    g_rowstart[NMAX + 1];
__device__ __align__(16) int    g_rank[EMAX];
__device__ __align__(16) unsigned long long g_lbstate[NB_MAX];
__device__ __align__(16) int    g_srcs[EMAX];
__device__ __align__(16) __half g_msg [(size_t)NMAX * 128];  // msg1 = (x@W1)*dinv
__device__ __align__(16) __half g_h1h [(size_t)NMAX * 128];  // h1 post-relu (fp16)
__device__ __align__(16) __half g_msg2[(size_t)NMAX * 64];   // msg2 = (h1@W2)*dinv

// ---------------- CSR build ----------------

__global__ void k_hist4(const int* __restrict__ dst, int* __restrict__ count,
                        int* __restrict__ rank, int E, int n) {
    int i = blockIdx.x * blockDim.x + threadIdx.x;
    int e = i * 4;
    if (e + 3 < E) {
        int4 d = *((const int4*)(dst + e));
        int4 r;
        r.x = ((unsigned)d.x < (unsigned)n) ? atomicAdd(&count[d.x], 1) : 0;
        r.y = ((unsigned)d.y < (unsigned)n) ? atomicAdd(&count[d.y], 1) : 0;
        r.z = ((unsigned)d.z < (unsigned)n) ? atomicAdd(&count[d.z], 1) : 0;
        r.w = ((unsigned)d.w < (unsigned)n) ? atomicAdd(&count[d.w], 1) : 0;
        *((int4*)(rank + e)) = r;
    } else if (e < E) {
        for (; e < E; e++) {
            int d = dst[e];
            rank[e] = ((unsigned)d < (unsigned)n) ? atomicAdd(&count[d], 1) : 0;
        }
    }
}

__device__ __forceinline__ unsigned long long ldv_u64(const unsigned long long* p) {
    unsigned long long v;
    asm volatile("ld.volatile.global.u64 %0, [%1];" : "=l"(v) : "l"(p));
    return v;
}

__global__ void k_scan_lb(const int* __restrict__ count, int* __restrict__ rowstart,
                          float* __restrict__ dinv, unsigned long long* __restrict__ state,
                          int n, int E) {
    __shared__ int wsum[32], wpre[32];
    __shared__ int prefix_s;
    const int tid = threadIdx.x;
    const int lane = tid & 31, wid = tid >> 5;
    const int b = blockIdx.x;
    const int i = b * SCAN_B + tid;
    int v = (i < n) ? count[i] : 0;

    int x = v;
#pragma unroll
    for (int off = 1; off < 32; off <<= 1) {
        int t = __shfl_up_sync(0xffffffffu, x, off);
        if (lane >= off) x += t;
    }
    if (lane == 31) wsum[wid] = x;
    __syncthreads();

    if (wid == 0) {
        int s = wsum[lane];
        int y = s;
#pragma unroll
        for (int off = 1; off < 32; off <<= 1) {
            int t = __shfl_up_sync(0xffffffffu, y, off);
            if (lane >= off) y += t;
        }
        wpre[lane] = y - s;
        int total = __shfl_sync(0xffffffffu, y, 31);

        if (lane == 0)
            atomicExch(&state[b], (1ull << 32) | (unsigned)total);

        int prefix = 0;
        if (b > 0) {
            int base = b;
            while (true) {
                int p = base - 1 - lane;
                int fl = 2, val = 0;
                if (p >= 0) {
                    unsigned long long s64;
                    do { s64 = ldv_u64(&state[p]); fl = (int)(s64 >> 32); } while (fl == 0);
                    val = (int)(unsigned)s64;
                }
                unsigned m2 = __ballot_sync(0xffffffffu, fl == 2);
                if (m2) {
                    int firstLane = __ffs(m2) - 1;
                    prefix += __reduce_add_sync(0xffffffffu, (lane <= firstLane) ? val : 0);
                    break;
                } else {
                    prefix += __reduce_add_sync(0xffffffffu, val);
                    base -= 32;
                }
            }
        }
        if (lane == 0) {
            atomicExch(&state[b], (2ull << 32) | (unsigned)(prefix + total));
            prefix_s = prefix;
        }
    }
    __syncthreads();

    int incl = x + wpre[wid];
    if (i < n) {
        rowstart[i] = incl - v + prefix_s;
        dinv[i] = rsqrtf((float)v + 1.0f);
    }
    if (b == gridDim.x - 1 && tid == 0) rowstart[n] = E;
}

__global__ void k_fill4(const int* __restrict__ src, const int* __restrict__ dst,
                        const int* __restrict__ rowstart, const int* __restrict__ rank,
                        int* __restrict__ srcs, int E, int n) {
    int i = blockIdx.x * blockDim.x + threadIdx.x;
    int e = i * 4;
    if (e + 3 < E) {
        int4 s4 = *((const int4*)(src + e));
        int4 d4 = *((const int4*)(dst + e));
        int4 r4 = *((const int4*)(rank + e));
        if ((unsigned)d4.x < (unsigned)n && (unsigned)s4.x < (unsigned)n) srcs[rowstart[d4.x] + r4.x] = s4.x;
        if ((unsigned)d4.y < (unsigned)n && (unsigned)s4.y < (unsigned)n) srcs[rowstart[d4.y] + r4.y] = s4.y;
        if ((unsigned)d4.z < (unsigned)n && (unsigned)s4.z < (unsigned)n) srcs[rowstart[d4.z] + r4.z] = s4.z;
        if ((unsigned)d4.w < (unsigned)n && (unsigned)s4.w < (unsigned)n) srcs[rowstart[d4.w] + r4.w] = s4.w;
    } else if (e < E) {
        for (; e < E; e++) {
            int d = dst[e], s = src[e];
            if ((unsigned)d < (unsigned)n && (unsigned)s < (unsigned)n)
                srcs[rowstart[d] + rank[e]] = s;
        }
    }
}

// ---------------- fp16 tensor-core GEMMs (mma.m16n8k16, fp32 accum) ----------------

#define MMA_F16(d, a, b)                                                        \
    asm volatile(                                                               \
        "mma.sync.aligned.m16n8k16.row.col.f32.f16.f16.f32 "                    \
        "{%0,%1,%2,%3}, {%4,%5,%6,%7}, {%8,%9}, {%0,%1,%2,%3};"                 \
        : "+f"((d)[0]), "+f"((d)[1]), "+f"((d)[2]), "+f"((d)[3])                \
        : "r"((a)[0]), "r"((a)[1]), "r"((a)[2]), "r"((a)[3]),                   \
          "r"((b)[0]), "r"((b)[1]))

// GEMM1: fp32 X, OUTC=128, dinv computed INLINE from count (depends on hist only).
__global__ void k_gemm1_tc(const float* __restrict__ X, const float* __restrict__ W,
                           const int* __restrict__ count, __half* __restrict__ out, int N) {
    constexpr int OUTC = 128, BM = 128;
    constexpr int AP2 = 20, OUTCP = OUTC + 4;
    constexpr int WARP_N = 64, NNT = WARP_N / 8;   // 8
    __shared__ uint32_t Ap[BM * AP2];
    __shared__ uint32_t Wsp[16 * OUTCP];

    const int tid  = threadIdx.x;
    const int warp = tid >> 5, lane = tid & 31;
    const int wm = warp >> 1, wn = warp & 1;
    const int g = lane >> 2, tig = lane & 3;
    const int rowBase = blockIdx.x * BM;

    float acc[2][NNT][4];
#pragma unroll
    for (int mt = 0; mt < 2; mt++)
#pragma unroll
        for (int nt = 0; nt < NNT; nt++)
#pragma unroll
            for (int c = 0; c < 4; c++) acc[mt][nt][c] = 0.f;

    for (int k0 = 0; k0 < 128; k0 += 32) {
#pragma unroll
        for (int j = 0; j < 4; j++) {
            int i4  = tid + j * 256;
            int row = i4 >> 3;
            int c4  = i4 & 7;
            float4 v = make_float4(0.f, 0.f, 0.f, 0.f);
            if (rowBase + row < N)
                v = *((const float4*)(X + (size_t)(rowBase + row) * 128 + k0 + c4 * 4));
            __half2 h0 = __floats2half2_rn(v.x, v.y);
            __half2 h1 = __floats2half2_rn(v.z, v.w);
            uint2 st;
            st.x = *(const uint32_t*)&h0;
            st.y = *(const uint32_t*)&h1;
            *((uint2*)&Ap[row * AP2 + c4 * 2]) = st;
        }
#pragma unroll
        for (int j = 0; j < 2; j++) {
            int i  = tid + j * 256;
            int k2 = i >> 5;
            int c  = (i & 31) * 4;
            float4 v0 = *((const float4*)(W + (size_t)(k0 + 2 * k2)     * OUTC + c));
            float4 v1 = *((const float4*)(W + (size_t)(k0 + 2 * k2 + 1) * OUTC + c));
            __half2 h0 = __floats2half2_rn(v0.x, v1.x);
            __half2 h1 = __floats2half2_rn(v0.y, v1.y);
            __half2 h2 = __floats2half2_rn(v0.z, v1.z);
            __half2 h3 = __floats2half2_rn(v0.w, v1.w);
            uint4 st;
            st.x = *(const uint32_t*)&h0; st.y = *(const uint32_t*)&h1;
            st.z = *(const uint32_t*)&h2; st.w = *(const uint32_t*)&h3;
            *((uint4*)&Wsp[k2 * OUTCP + c]) = st;
        }
        __syncthreads();

#pragma unroll
        for (int kk = 0; kk < 2; kk++) {
            int k2b = kk * 8;
            uint32_t a[2][4];
#pragma unroll
            for (int mt = 0; mt < 2; mt++) {
                int ar = wm * 32 + mt * 16;
                a[mt][0] = Ap[(ar + g)     * AP2 + k2b + tig];
                a[mt][1] = Ap[(ar + g + 8) * AP2 + k2b + tig];
                a[mt][2] = Ap[(ar + g)     * AP2 + k2b + 4 + tig];
                a[mt][3] = Ap[(ar + g + 8) * AP2 + k2b + 4 + tig];
            }
#pragma unroll
            for (int nt = 0; nt < NNT; nt++) {
                int nc = wn * WARP_N + nt * 8;
                uint32_t b[2];
                b[0] = Wsp[(k2b + tig)     * OUTCP + nc + g];
                b[1] = Wsp[(k2b + 4 + tig) * OUTCP + nc + g];
#pragma unroll
                for (int mt = 0; mt < 2; mt++) MMA_F16(acc[mt][nt], a[mt], b);
            }
        }
        __syncthreads();
    }

#pragma unroll
    for (int mt = 0; mt < 2; mt++) {
        int r0 = rowBase + wm * 32 + mt * 16 + g;
        int r1 = r0 + 8;
        float dv0 = (r0 < N) ? rsqrtf((float)count[r0] + 1.0f) : 0.f;
        float dv1 = (r1 < N) ? rsqrtf((float)count[r1] + 1.0f) : 0.f;
#pragma unroll
        for (int nt = 0; nt < NNT; nt++) {
            int col = wn * WARP_N + nt * 8 + tig * 2;
            if (r0 < N)
                *((__half2*)(out + (size_t)r0 * OUTC + col)) =
                    __floats2half2_rn(acc[mt][nt][0] * dv0, acc[mt][nt][1] * dv0);
            if (r1 < N)
                *((__half2*)(out + (size_t)r1 * OUTC + col)) =
                    __floats2half2_rn(acc[mt][nt][2] * dv1, acc[mt][nt][3] * dv1);
        }
    }
}

// GEMM2: fp16 input, OUTC=64, dinv from array.
__global__ void k_gemm2_tc(const __half* __restrict__ Xh, const float* __restrict__ W,
                           const float* __restrict__ dinv, __half* __restrict__ out,
                           int Nrows) {
    constexpr int OUTC = 64, BM = 128;
    constexpr int AP2 = 20, OUTCP = OUTC + 4;
    constexpr int WARP_N = 32, NNT = WARP_N / 8;   // 4
    __shared__ uint32_t Ap[BM * AP2];
    __shared__ uint32_t Wsp[16 * OUTCP];

    const int tid  = threadIdx.x;
    const int warp = tid >> 5, lane = tid & 31;
    const int wm = warp >> 1, wn = warp & 1;
    const int g = lane >> 2, tig = lane & 3;
    const int rowBase = blockIdx.x * BM;

    float acc[2][NNT][4];
#pragma unroll
    for (int mt = 0; mt < 2; mt++)
#pragma unroll
        for (int nt = 0; nt < NNT; nt++)
#pragma unroll
            for (int c = 0; c < 4; c++) acc[mt][nt][c] = 0.f;

    for (int k0 = 0; k0 < 128; k0 += 32) {
#pragma unroll
        for (int j = 0; j < 2; j++) {
            int i4  = tid + j * 256;
            int row = i4 >> 2;
            int q   = i4 & 3;
            uint4 u = make_uint4(0, 0, 0, 0);
            if (rowBase + row < Nrows)
                u = *((const uint4*)(Xh + (size_t)(rowBase + row) * 128 + k0 + q * 8));
            *((uint4*)&Ap[row * AP2 + q * 4]) = u;
        }
        {
            int i  = tid;
            int k2 = i >> 4;
            int c  = (i & 15) * 4;
            float4 v0 = *((const float4*)(W + (size_t)(k0 + 2 * k2)     * OUTC + c));
            float4 v1 = *((const float4*)(W + (size_t)(k0 + 2 * k2 + 1) * OUTC + c));
            __half2 h0 = __floats2half2_rn(v0.x, v1.x);
            __half2 h1 = __floats2half2_rn(v0.y, v1.y);
            __half2 h2 = __floats2half2_rn(v0.z, v1.z);
            __half2 h3 = __floats2half2_rn(v0.w, v1.w);
            uint4 st;
            st.x = *(const uint32_t*)&h0; st.y = *(const uint32_t*)&h1;
            st.z = *(const uint32_t*)&h2; st.w = *(const uint32_t*)&h3;
            *((uint4*)&Wsp[k2 * OUTCP + c]) = st;
        }
        __syncthreads();

#pragma unroll
        for (int kk = 0; kk < 2; kk++) {
            int k2b = kk * 8;
            uint32_t a[2][4];
#pragma unroll
            for (int mt = 0; mt < 2; mt++) {
                int ar = wm * 32 + mt * 16;
                a[mt][0] = Ap[(ar + g)     * AP2 + k2b + tig];
                a[mt][1] = Ap[(ar + g + 8) * AP2 + k2b + tig];
                a[mt][2] = Ap[(ar + g)     * AP2 + k2b + 4 + tig];
                a[mt][3] = Ap[(ar + g + 8) * AP2 + k2b + 4 + tig];
            }
#pragma unroll
            for (int nt = 0; nt < NNT; nt++) {
                int nc = wn * WARP_N + nt * 8;
                uint32_t b[2];
                b[0] = Wsp[(k2b + tig)     * OUTCP + nc + g];
                b[1] = Wsp[(k2b + 4 + tig) * OUTCP + nc + g];
#pragma unroll
                for (int mt = 0; mt < 2; mt++) MMA_F16(acc[mt][nt], a[mt], b);
            }
        }
        __syncthreads();
    }

#pragma unroll
    for (int mt = 0; mt < 2; mt++) {
        int r0 = rowBase + wm * 32 + mt * 16 + g;
        int r1 = r0 + 8;
        float dv0 = (r0 < Nrows) ? dinv[r0] : 0.f;
        float dv1 = (r1 < Nrows) ? dinv[r1] : 0.f;
#pragma unroll
        for (int nt = 0; nt < NNT; nt++) {
            int col = wn * WARP_N + nt * 8 + tig * 2;
            if (r0 < Nrows)
                *((__half2*)(out + (size_t)r0 * OUTC + col)) =
                    __floats2half2_rn(acc[mt][nt][0] * dv0, acc[mt][nt][1] * dv0);
            if (r1 < Nrows)
                *((__half2*)(out + (size_t)r1 * OUTC + col)) =
                    __floats2half2_rn(acc[mt][nt][2] * dv1, acc[mt][nt][3] * dv1);
        }
    }
}

// ---------------- gathers ----------------
// Layer 1: msg pre-scaled by dinv[src]. h1h = half(relu((Σ msg[s] + msg[n])·dinv[n] + b1))
// Epilogue also re-zeros count[] and lbstate[] for the NEXT call (graph replay).

__global__ void k_gather128h(const __half* __restrict__ g, const int* __restrict__ rowstart,
                             const int* __restrict__ srcs, const float* __restrict__ dinv,
                             const float* __restrict__ bias, __half* __restrict__ out,
                             int* __restrict__ count, int* __restrict__ lbstate_i, int n) {
    // zero the lookback state for next call (block 0 only; 64 u64 = 128 ints)
    if (blockIdx.x == 0 && threadIdx.x < NB_MAX * 2)
        lbstate_i[threadIdx.x] = 0;

    int node = (blockIdx.x * blockDim.x + threadIdx.x) >> 5;
    int lane = threadIdx.x & 31;
    if (node >= n) return;
    int e0 = rowstart[node], e1 = rowstart[node + 1];
    float dvn = dinv[node];
    if (lane == 0) count[node] = 0;   // reset for next call (hist re-accumulates)

    float acc0, acc1, acc2, acc3;
    {
        uint2 u = *((const uint2*)(g + (size_t)node * 128 + lane * 4));
        float2 a = __half22float2(*(const __half2*)&u.x);
        float2 b = __half22float2(*(const __half2*)&u.y);
        acc0 = a.x; acc1 = a.y; acc2 = b.x; acc3 = b.y;
    }
    int e = e0;
    while (e1 - e >= 32) {
        int idx = srcs[e + lane];
#pragma unroll
        for (int k = 0; k < 32; k++) {
            int s = __shfl_sync(0xffffffffu, idx, k);
            uint2 u = *((const uint2*)(g + (size_t)s * 128 + lane * 4));
            float2 a = __half22float2(*(const __half2*)&u.x);
            float2 b = __half22float2(*(const __half2*)&u.y);
            acc0 += a.x; acc1 += a.y; acc2 += b.x; acc3 += b.y;
        }
        e += 32;
    }
    if (e < e1) {
        int m = e1 - e;
        int idx = (lane < m) ? srcs[e + lane] : 0;
#pragma unroll 8
        for (int k = 0; k < m; k++) {
            int s = __shfl_sync(0xffffffffu, idx, k);
            uint2 u = *((const uint2*)(g + (size_t)s * 128 + lane * 4));
            float2 a = __half22float2(*(const __half2*)&u.x);
            float2 b = __half22float2(*(const __half2*)&u.y);
            acc0 += a.x; acc1 += a.y; acc2 += b.x; acc3 += b.y;
        }
    }
    float4 bv = ((const float4*)bias)[lane];
    __half2 h01 = __floats2half2_rn(fmaxf(acc0 * dvn + bv.x, 0.f),
                                    fmaxf(acc1 * dvn + bv.y, 0.f));
    __half2 h23 = __floats2half2_rn(fmaxf(acc2 * dvn + bv.z, 0.f),
                                    fmaxf(acc3 * dvn + bv.w, 0.f));
    uint2 st;
    st.x = *(const uint32_t*)&h01;
    st.y = *(const uint32_t*)&h23;
    *((uint2*)(out + (size_t)node * 128 + lane * 4)) = st;
}

// Layer 2: out = (Σ msg2[s] + msg2[n])·dinv[n] + b2
__global__ void k_gather64h(const __half* __restrict__ g, const int* __restrict__ rowstart,
                            const int* __restrict__ srcs, const float* __restrict__ dinv,
                            const float* __restrict__ bias, float* __restrict__ out, int n) {
    int node = (blockIdx.x * blockDim.x + threadIdx.x) >> 5;
    int lane = threadIdx.x & 31;
    if (node >= n) return;
    int e0 = rowstart[node], e1 = rowstart[node + 1];

    float2 acc = __half22float2(*((const __half2*)(g + (size_t)node * 64 + lane * 2)));
    int e = e0;
    while (e1 - e >= 32) {
        int idx = srcs[e + lane];
#pragma unroll
        for (int k = 0; k < 32; k++) {
            int s = __shfl_sync(0xffffffffu, idx, k);
            float2 v = __half22float2(*((const __half2*)(g + (size_t)s * 64 + lane * 2)));
            acc.x += v.x; acc.y += v.y;
        }
        e += 32;
    }
    if (e < e1) {
        int m = e1 - e;
        int idx = (lane < m) ? srcs[e + lane] : 0;
#pragma unroll 8
        for (int k = 0; k < m; k++) {
            int s = __shfl_sync(0xffffffffu, idx, k);
            float2 v = __half22float2(*((const __half2*)(g + (size_t)s * 64 + lane * 2)));
            acc.x += v.x; acc.y += v.y;
        }
    }
    float dv = dinv[node];
    float2 bv = ((const float2*)bias)[lane];
    float2 r;
    r.x = acc.x * dv + bv.x;
    r.y = acc.y * dv + bv.y;
    ((float2*)(out + (size_t)node * 64))[lane] = r;
}

// ---------------- launch ----------------

extern "C" void kernel_launch(void* const* d_in, const int* in_sizes, int n_in,
                              void* d_out, int out_size) {
    const float* x   = (const float*)d_in[0];
    const int*   ei  = (const int*)d_in[1];    // int32 (JAX x64 disabled)
    const float* W1  = (const float*)d_in[2];
    const float* b1  = (const float*)d_in[3];
    const float* W2  = (const float*)d_in[4];
    const float* b2  = (const float*)d_in[5];
    float*       out = (float*)d_out;

    const int N = in_sizes[0] / 128;
    const int E = in_sizes[1] / 2;
    const int* srcp = ei;
    const int* dstp = ei + E;

    float*  dinv;  cudaGetSymbolAddress((void**)&dinv,  g_dinv);
    int*    count; cudaGetSymbolAddress((void**)&count, g_count);
    int*    rowst; cudaGetSymbolAddress((void**)&rowst, g_rowstart);
    int*    rank;  cudaGetSymbolAddress((void**)&rank,  g_rank);
    unsigned long long* lbst; cudaGetSymbolAddress((void**)&lbst, g_lbstate);
    int*    srcs;  cudaGetSymbolAddress((void**)&srcs,  g_srcs);
    __half* msg;   cudaGetSymbolAddress((void**)&msg,   g_msg);
    __half* h1h;   cudaGetSymbolAddress((void**)&h1h,   g_h1h);
    __half* msg2;  cudaGetSymbolAddress((void**)&msg2,  g_msg2);

    static cudaStream_t s2 = nullptr;
    static cudaEvent_t evH = nullptr, evG1 = nullptr;
    if (!s2) {
        cudaStreamCreateWithFlags(&s2, cudaStreamNonBlocking);
        cudaEventCreateWithFlags(&evH, cudaEventDisableTiming);
        cudaEventCreateWithFlags(&evG1, cudaEventDisableTiming);
    }

    const int T = 256;
    const int nb = (N + SCAN_B - 1) / SCAN_B;   // 49

    // stream 0: hist (count/lbstate are pre-zeroed by previous call / static init)
    k_hist4<<<(E / 4 + T) / T, T>>>(dstp, count, rank, E, N);
    cudaEventRecord(evH, 0);

    // fork: GEMM1 (needs only count — dinv computed inline) overlaps scan+fill
    cudaStreamWaitEvent(s2, evH, 0);
    k_gemm1_tc<<<(N + 127) / 128, 256, 0, s2>>>(x, W1, count, msg, N);
    cudaEventRecord(evG1, s2);

    // stream 0: scan -> fill
    k_scan_lb<<<nb, SCAN_B>>>(count, rowst, dinv, lbst, N, E);
    k_fill4<<<(E / 4 + T) / T, T>>>(srcp, dstp, rowst, rank, srcs, E, N);

    // join: gather1 needs fill + scan (stream 0) + GEMM1 (s2); its epilogue
    // re-zeros count/lbstate for the next call
    cudaStreamWaitEvent(0, evG1, 0);
    k_gather128h<<<(N * 32 + T - 1) / T, T>>>(msg, rowst, srcs, dinv, b1, h1h,
                                              count, (int*)lbst, N);

    // layer 2
    k_gemm2_tc<<<(N + 127) / 128, 256>>>(h1h, W2, dinv, msg2, N);
    k_gather64h<<<(N * 32 + T - 1) / T, T>>>(msg2, rowst, srcs, dinv, b2, out, N);
}